// round 1
// baseline (speedup 1.0000x reference)
#include <cuda_runtime.h>
#include <math.h>

namespace {
constexpr int D = 512;
constexpr int L = 48;
constexpr int NPATCH = 8 * 7 * 24;     // 1344 patches
constexpr int MTOT = NPATCH * L;       // 64512 rows
constexpr int BM = 128, BN = 64, BK = 16;
}

// Scratch (static device allocations are allowed; cudaMalloc is not)
__device__ float g_q[(size_t)MTOT * D];
__device__ float g_k[(size_t)MTOT * D];
__device__ float g_v[(size_t)MTOT * D];
__device__ float g_o[(size_t)MTOT * D];

// ---------------------------------------------------------------------------
// C[m][n] = sum_d A[m][d] * W[n][d] + bias[n]      (A: [MTOT,D], W: [D,D])
// BM=128 x BN=64 tile, BK=16, 256 threads, 8x4 register tile per thread.
// ---------------------------------------------------------------------------
__device__ __forceinline__ void gemm_body(
    const float* __restrict__ A, const float* __restrict__ W,
    const float* __restrict__ bias, float* __restrict__ C)
{
    __shared__ __align__(16) float As[BK][BM];
    __shared__ __align__(16) float Bs[BK][BN];

    const int tid = threadIdx.x;
    const int tx = tid & 15;   // 16 col-groups of 4
    const int ty = tid >> 4;   // 16 row-groups of 8
    const int m0 = blockIdx.x * BM;
    const int n0 = blockIdx.y * BN;

    float acc[8][4];
#pragma unroll
    for (int i = 0; i < 8; i++)
#pragma unroll
        for (int j = 0; j < 4; j++) acc[i][j] = 0.0f;

    for (int k0 = 0; k0 < D; k0 += BK) {
        // Load A tile: 128x16 = 512 float4, 2 per thread, stored transposed.
#pragma unroll
        for (int r = 0; r < 2; r++) {
            int id = tid + r * 256;
            int row = id >> 2;
            int c4 = id & 3;
            float4 v = *(const float4*)(A + (size_t)(m0 + row) * D + k0 + c4 * 4);
            As[c4 * 4 + 0][row] = v.x;
            As[c4 * 4 + 1][row] = v.y;
            As[c4 * 4 + 2][row] = v.z;
            As[c4 * 4 + 3][row] = v.w;
        }
        // Load W tile: 64x16 = 256 float4, 1 per thread, stored transposed.
        {
            int row = tid >> 2;
            int c4 = tid & 3;
            float4 v = *(const float4*)(W + (size_t)(n0 + row) * D + k0 + c4 * 4);
            Bs[c4 * 4 + 0][row] = v.x;
            Bs[c4 * 4 + 1][row] = v.y;
            Bs[c4 * 4 + 2][row] = v.z;
            Bs[c4 * 4 + 3][row] = v.w;
        }
        __syncthreads();

#pragma unroll
        for (int kk = 0; kk < BK; kk++) {
            float4 a0 = *(const float4*)&As[kk][ty * 8];
            float4 a1 = *(const float4*)&As[kk][ty * 8 + 4];
            float4 b0 = *(const float4*)&Bs[kk][tx * 4];
            float a[8] = {a0.x, a0.y, a0.z, a0.w, a1.x, a1.y, a1.z, a1.w};
            float b[4] = {b0.x, b0.y, b0.z, b0.w};
#pragma unroll
            for (int i = 0; i < 8; i++)
#pragma unroll
                for (int j = 0; j < 4; j++)
                    acc[i][j] = fmaf(a[i], b[j], acc[i][j]);
        }
        __syncthreads();
    }

    const int col = n0 + tx * 4;
    float4 bb = *(const float4*)(bias + col);
#pragma unroll
    for (int i = 0; i < 8; i++) {
        int row = m0 + ty * 8 + i;
        float4 o;
        o.x = acc[i][0] + bb.x;
        o.y = acc[i][1] + bb.y;
        o.z = acc[i][2] + bb.z;
        o.w = acc[i][3] + bb.w;
        *(float4*)(C + (size_t)row * D + col) = o;
    }
}

__global__ __launch_bounds__(256) void qkv_proj_kernel(
    const float* __restrict__ queries, const float* __restrict__ keys,
    const float* __restrict__ values, const float* __restrict__ Wq,
    const float* __restrict__ bq, const float* __restrict__ Wkv,
    const float* __restrict__ bkv)
{
    int z = blockIdx.z;
    const float* A = (z == 0) ? queries : (z == 1) ? keys : values;
    const float* W = (z == 0) ? Wq : Wkv;
    const float* b = (z == 0) ? bq : bkv;
    float* C = (z == 0) ? g_q : (z == 1) ? g_k : g_v;
    gemm_body(A, W, b, C);
}

__global__ __launch_bounds__(256) void out_proj_kernel(
    const float* __restrict__ Wo, const float* __restrict__ bo,
    float* __restrict__ out)
{
    gemm_body(g_o, Wo, bo, out);
}

// ---------------------------------------------------------------------------
// Fused per-patch attention. One block per patch (1344 blocks, 256 threads).
//   S = q k^T  (48x48, fp32 regs, 3x3 per thread over a 16x16 thread grid)
//   mask diag = -inf, softmax(scale * S)
//   out = attn @ v
// ---------------------------------------------------------------------------
__global__ __launch_bounds__(256) void attn_kernel()
{
    const int patch = blockIdx.x;
    const size_t base = (size_t)patch * L * D;
    const float* q = g_q + base;
    const float* k = g_k + base;
    const float* v = g_v + base;
    float* o = g_o + base;

    __shared__ __align__(16) float qs[64 * 49];   // transposed chunks [dk][48]
    __shared__ __align__(16) float ks[64 * 49];
    __shared__ float Ss[48][49];

    const int tid = threadIdx.x;
    const int tx = tid & 15;   // 16 * 3 = 48 cols
    const int ty = tid >> 4;   // 16 * 3 = 48 rows

    float s[3][3];
#pragma unroll
    for (int i = 0; i < 3; i++)
#pragma unroll
        for (int j = 0; j < 3; j++) s[i][j] = 0.0f;

    // ---- Stage 1: S = q k^T, tiled over D in chunks of 64 ----
    for (int d0 = 0; d0 < D; d0 += 64) {
        // 48 rows x 16 float4 = 768 float4 each for q and k; 3 per thread.
#pragma unroll
        for (int r = 0; r < 3; r++) {
            int id = tid + r * 256;
            int row = id >> 4;   // 0..47
            int c4 = id & 15;
            float4 vq = *(const float4*)(q + (size_t)row * D + d0 + c4 * 4);
            float4 vk = *(const float4*)(k + (size_t)row * D + d0 + c4 * 4);
            qs[(c4 * 4 + 0) * 49 + row] = vq.x;
            qs[(c4 * 4 + 1) * 49 + row] = vq.y;
            qs[(c4 * 4 + 2) * 49 + row] = vq.z;
            qs[(c4 * 4 + 3) * 49 + row] = vq.w;
            ks[(c4 * 4 + 0) * 49 + row] = vk.x;
            ks[(c4 * 4 + 1) * 49 + row] = vk.y;
            ks[(c4 * 4 + 2) * 49 + row] = vk.z;
            ks[(c4 * 4 + 3) * 49 + row] = vk.w;
        }
        __syncthreads();
#pragma unroll 4
        for (int kk = 0; kk < 64; kk++) {
            float a0 = qs[kk * 49 + ty * 3 + 0];
            float a1 = qs[kk * 49 + ty * 3 + 1];
            float a2 = qs[kk * 49 + ty * 3 + 2];
            float b0 = ks[kk * 49 + tx * 3 + 0];
            float b1 = ks[kk * 49 + tx * 3 + 1];
            float b2 = ks[kk * 49 + tx * 3 + 2];
            s[0][0] = fmaf(a0, b0, s[0][0]);
            s[0][1] = fmaf(a0, b1, s[0][1]);
            s[0][2] = fmaf(a0, b2, s[0][2]);
            s[1][0] = fmaf(a1, b0, s[1][0]);
            s[1][1] = fmaf(a1, b1, s[1][1]);
            s[1][2] = fmaf(a1, b2, s[1][2]);
            s[2][0] = fmaf(a2, b0, s[2][0]);
            s[2][1] = fmaf(a2, b1, s[2][1]);
            s[2][2] = fmaf(a2, b2, s[2][2]);
        }
        __syncthreads();
    }

    // ---- Stage 2: mask + scale into smem, then row softmax ----
    const float scale = 0.044194173824159216f;   // 512^-0.5
#pragma unroll
    for (int i = 0; i < 3; i++)
#pragma unroll
        for (int j = 0; j < 3; j++) {
            int row = ty * 3 + i;
            int col = tx * 3 + j;
            Ss[row][col] = (row == col) ? -INFINITY : s[i][j] * scale;
        }
    __syncthreads();

    if (tid < 48) {
        float m = -INFINITY;
#pragma unroll
        for (int c = 0; c < 48; c++) m = fmaxf(m, Ss[tid][c]);
        float sum = 0.0f;
#pragma unroll
        for (int c = 0; c < 48; c++) {
            float e = __expf(Ss[tid][c] - m);
            Ss[tid][c] = e;
            sum += e;
        }
        float inv = 1.0f / sum;
#pragma unroll
        for (int c = 0; c < 48; c++) Ss[tid][c] *= inv;
    }
    __syncthreads();

    // ---- Stage 3: out = attn @ v, tiled over D in chunks of 64 ----
    float* vs = qs;   // reuse; need 48*64 = 3072 <= 64*49 floats
    const int dcol = tid & 63;
    const int lg = tid >> 6;   // 0..3
    for (int d0 = 0; d0 < D; d0 += 64) {
#pragma unroll
        for (int r = 0; r < 3; r++) {
            int id = tid + r * 256;
            int row = id >> 4;
            int c4 = id & 15;
            *(float4*)&vs[row * 64 + c4 * 4] =
                *(const float4*)(v + (size_t)row * D + d0 + c4 * 4);
        }
        __syncthreads();
#pragma unroll
        for (int lb = 0; lb < 12; lb++) {
            int l = lb * 4 + lg;
            float acc = 0.0f;
#pragma unroll
            for (int m = 0; m < 48; m++)
                acc = fmaf(Ss[l][m], vs[m * 64 + dcol], acc);
            o[(size_t)l * D + d0 + dcol] = acc;
        }
        __syncthreads();
    }
}

// ---------------------------------------------------------------------------
extern "C" void kernel_launch(void* const* d_in, const int* in_sizes, int n_in,
                              void* d_out, int out_size)
{
    const float* queries = (const float*)d_in[0];
    const float* keys    = (const float*)d_in[1];
    const float* values  = (const float*)d_in[2];
    const float* Wq      = (const float*)d_in[3];
    const float* bq      = (const float*)d_in[4];
    const float* Wkv     = (const float*)d_in[5];
    const float* bkv     = (const float*)d_in[6];
    const float* Wo      = (const float*)d_in[7];
    const float* bo      = (const float*)d_in[8];
    float* out = (float*)d_out;

    dim3 gqkv(MTOT / BM, D / BN, 3);
    qkv_proj_kernel<<<gqkv, 256>>>(queries, keys, values, Wq, bq, Wkv, bkv);

    attn_kernel<<<NPATCH, 256>>>();

    dim3 gout(MTOT / BM, D / BN);
    out_proj_kernel<<<gout, 256>>>(Wo, bo, out);
}

// round 3
// speedup vs baseline: 2.0242x; 2.0242x over previous
#include <cuda_runtime.h>
#include <cuda_bf16.h>
#include <math.h>
#include <stdint.h>

// ============================================================================
// Problem constants
// ============================================================================
namespace {
constexpr int D = 512;
constexpr int L = 48;
constexpr int NPATCH = 8 * 7 * 24;     // 1344
constexpr int MTOT = NPATCH * L;       // 64512
constexpr int BM = 128, BN = 128;
constexpr int BK = 32;                 // bf16 elems per chunk
constexpr int NCH = (D / BK) * 3;      // 48 extended-K chunks (3 split terms)
constexpr int NS = 3;                  // pipeline stages
constexpr int ROWB = 80;               // smem row stride bytes (32*2 + 16 pad)
constexpr int TILEB = 128 * ROWB;      // 10240 per tile
constexpr int STAGEB = 2 * TILEB;      // A + B
constexpr int SMEM_DYN = NS * STAGEB;  // 61440
}

// ============================================================================
// Scratch (__device__ globals; no cudaMalloc allowed)
// ============================================================================
__device__ __nv_bfloat16 g_xqh[(size_t)MTOT * D], g_xql[(size_t)MTOT * D];
__device__ __nv_bfloat16 g_xkh[(size_t)MTOT * D], g_xkl[(size_t)MTOT * D];
__device__ __nv_bfloat16 g_xvh[(size_t)MTOT * D], g_xvl[(size_t)MTOT * D];
__device__ __nv_bfloat16 g_qh[(size_t)MTOT * D],  g_ql[(size_t)MTOT * D];
__device__ __nv_bfloat16 g_kh[(size_t)MTOT * D],  g_kl[(size_t)MTOT * D];
__device__ __nv_bfloat16 g_vh[(size_t)MTOT * D],  g_vl[(size_t)MTOT * D];
__device__ __nv_bfloat16 g_oh[(size_t)MTOT * D],  g_ol[(size_t)MTOT * D];
__device__ __nv_bfloat16 g_wqh[D * D], g_wql[D * D];
__device__ __nv_bfloat16 g_wkh[D * D], g_wkl[D * D];
__device__ __nv_bfloat16 g_woh[D * D], g_wol[D * D];

// ============================================================================
// PTX helpers (baseline sm_90-compatible only; NO tcgen05 — harness PTX
// targets compute_103 without the 'a' suffix, so arch-specific ops are
// rejected by ptxas)
// ============================================================================
__device__ __forceinline__ uint32_t smem_u32(const void* p) {
    uint32_t a;
    asm("{ .reg .u64 t; cvta.to.shared.u64 t, %1; cvt.u32.u64 %0, t; }"
        : "=r"(a) : "l"(p));
    return a;
}
__device__ __forceinline__ void cp_async16(uint32_t dst, const void* src) {
    asm volatile("cp.async.cg.shared.global [%0], [%1], 16;" :: "r"(dst), "l"(src));
}
__device__ __forceinline__ void cp_commit() {
    asm volatile("cp.async.commit_group;" ::: "memory");
}
template <int N>
__device__ __forceinline__ void cp_wait() {
    asm volatile("cp.async.wait_group %0;" :: "n"(N) : "memory");
}
__device__ __forceinline__ void ldsm4(uint32_t* r, uint32_t addr) {
    asm volatile("ldmatrix.sync.aligned.m8n8.x4.shared.b16 {%0,%1,%2,%3}, [%4];"
                 : "=r"(r[0]), "=r"(r[1]), "=r"(r[2]), "=r"(r[3]) : "r"(addr));
}
__device__ __forceinline__ void mma16816(float* c, const uint32_t* a,
                                         const uint32_t* b) {
    asm volatile(
        "mma.sync.aligned.m16n8k16.row.col.f32.bf16.bf16.f32 "
        "{%0,%1,%2,%3}, {%4,%5,%6,%7}, {%8,%9}, {%0,%1,%2,%3};"
        : "+f"(c[0]), "+f"(c[1]), "+f"(c[2]), "+f"(c[3])
        : "r"(a[0]), "r"(a[1]), "r"(a[2]), "r"(a[3]), "r"(b[0]), "r"(b[1]));
}

// ============================================================================
// fp32 -> bf16 hi/lo split
// ============================================================================
__device__ __forceinline__ void split4(const float4 x, ushort4& h, ushort4& l) {
    float xs[4] = {x.x, x.y, x.z, x.w};
    unsigned short hv[4], lv[4];
#pragma unroll
    for (int j = 0; j < 4; j++) {
        __nv_bfloat16 hh = __float2bfloat16(xs[j]);
        float r = xs[j] - __bfloat162float(hh);
        hv[j] = __bfloat16_as_ushort(hh);
        lv[j] = __bfloat16_as_ushort(__float2bfloat16(r));
    }
    h = make_ushort4(hv[0], hv[1], hv[2], hv[3]);
    l = make_ushort4(lv[0], lv[1], lv[2], lv[3]);
}
__device__ __forceinline__ void store_split2(__nv_bfloat16* H, __nv_bfloat16* L,
                                             size_t idx, float v0, float v1) {
    __nv_bfloat16 h0 = __float2bfloat16(v0);
    __nv_bfloat16 h1 = __float2bfloat16(v1);
    __nv_bfloat162 hh; hh.x = h0; hh.y = h1;
    *(__nv_bfloat162*)(H + idx) = hh;
    __nv_bfloat162 ll;
    ll.x = __float2bfloat16(v0 - __bfloat162float(h0));
    ll.y = __float2bfloat16(v1 - __bfloat162float(h1));
    *(__nv_bfloat162*)(L + idx) = ll;
}
__device__ __forceinline__ float4 ld4_split(const __nv_bfloat16* H,
                                            const __nv_bfloat16* L, size_t idx) {
    ushort4 h = *(const ushort4*)(H + idx);
    ushort4 l = *(const ushort4*)(L + idx);
    float4 r;
    r.x = __bfloat162float(__ushort_as_bfloat16(h.x)) +
          __bfloat162float(__ushort_as_bfloat16(l.x));
    r.y = __bfloat162float(__ushort_as_bfloat16(h.y)) +
          __bfloat162float(__ushort_as_bfloat16(l.y));
    r.z = __bfloat162float(__ushort_as_bfloat16(h.z)) +
          __bfloat162float(__ushort_as_bfloat16(l.z));
    r.w = __bfloat162float(__ushort_as_bfloat16(h.w)) +
          __bfloat162float(__ushort_as_bfloat16(l.w));
    return r;
}

__global__ __launch_bounds__(256) void conv_inputs(
    const float* __restrict__ q, const float* __restrict__ k,
    const float* __restrict__ v)
{
    size_t i4 = (size_t)blockIdx.x * 256 + threadIdx.x;
    size_t idx = i4 * 4;
    ushort4 h, l;
    split4(((const float4*)q)[i4], h, l);
    *(ushort4*)(g_xqh + idx) = h; *(ushort4*)(g_xql + idx) = l;
    split4(((const float4*)k)[i4], h, l);
    *(ushort4*)(g_xkh + idx) = h; *(ushort4*)(g_xkl + idx) = l;
    split4(((const float4*)v)[i4], h, l);
    *(ushort4*)(g_xvh + idx) = h; *(ushort4*)(g_xvl + idx) = l;
}

__global__ __launch_bounds__(256) void conv_weights(
    const float* __restrict__ wq, const float* __restrict__ wkv,
    const float* __restrict__ wo)
{
    size_t i4 = (size_t)blockIdx.x * 256 + threadIdx.x;
    size_t idx = i4 * 4;
    ushort4 h, l;
    split4(((const float4*)wq)[i4], h, l);
    *(ushort4*)(g_wqh + idx) = h; *(ushort4*)(g_wql + idx) = l;
    split4(((const float4*)wkv)[i4], h, l);
    *(ushort4*)(g_wkh + idx) = h; *(ushort4*)(g_wkl + idx) = l;
    split4(((const float4*)wo)[i4], h, l);
    *(ushort4*)(g_woh + idx) = h; *(ushort4*)(g_wol + idx) = l;
}

// ============================================================================
// HMMA GEMM: C[m][n] = sum_d A[m][d]*W[n][d] + bias[n], bf16x3 split via
// extended K (chunk c: term t=c%3, k0=(c/3)*BK; sources (Ahi,Bhi),(Ahi,Blo),
// (Alo,Bhi)). fp32 accumulate in registers.
// ============================================================================
template <bool WriteSplit>
__device__ __forceinline__ void gemm_body(
    const __nv_bfloat16* __restrict__ Ahi, const __nv_bfloat16* __restrict__ Alo,
    const __nv_bfloat16* __restrict__ Bhi, const __nv_bfloat16* __restrict__ Blo,
    const float* __restrict__ bias, float* __restrict__ Cf,
    __nv_bfloat16* __restrict__ Ch, __nv_bfloat16* __restrict__ Cl)
{
    extern __shared__ __align__(16) char dsm[];
    const uint32_t smem = smem_u32(dsm);
    __shared__ float bias_s[BN];

    const int tid = threadIdx.x;
    const int wid = tid >> 5, lane = tid & 31;
    const int wm = wid & 1, wn = wid >> 1;           // 2 x 4 warp grid
    const int n0 = blockIdx.x * BN;
    const int m0 = blockIdx.y * BM;

    if (tid < BN) bias_s[tid] = bias[n0 + tid];

    float acc[4][4][4];
#pragma unroll
    for (int i = 0; i < 4; i++)
#pragma unroll
        for (int j = 0; j < 4; j++)
#pragma unroll
            for (int e = 0; e < 4; e++) acc[i][j][e] = 0.0f;

    auto load_chunk = [&](int c) {
        const int s = c % NS;
        const int t = c % 3;
        const int k0 = (c / 3) * BK;
        const __nv_bfloat16* sA = (t < 2) ? Ahi : Alo;
        const __nv_bfloat16* sB = (t == 1) ? Blo : Bhi;
        const uint32_t stA = smem + (uint32_t)s * STAGEB;
        const uint32_t stB = stA + TILEB;
        const int row = tid >> 2;        // 0..63 (+64 second half)
        const int c16 = tid & 3;         // 16B granule in row
#pragma unroll
        for (int r = 0; r < 2; r++) {
            int rr = row + r * 64;
            cp_async16(stA + rr * ROWB + c16 * 16,
                       sA + (size_t)(m0 + rr) * D + k0 + c16 * 8);
        }
#pragma unroll
        for (int r = 0; r < 2; r++) {
            int rr = row + r * 64;
            cp_async16(stB + rr * ROWB + c16 * 16,
                       sB + (size_t)(n0 + rr) * D + k0 + c16 * 8);
        }
        cp_commit();
    };

    load_chunk(0);
    load_chunk(1);
    load_chunk(2);

    // ldmatrix lane address components
    const uint32_t aLaneRow = (uint32_t)(wm * 64 + (lane & 15));
    const uint32_t aLaneOff = (uint32_t)(((lane >> 4) & 1) * 16);
    const uint32_t bLaneRow = (uint32_t)(wn * 32 + ((lane >> 4) & 1) * 8 + (lane & 7));
    const uint32_t bLaneOff = (uint32_t)(((lane >> 3) & 1) * 16);

    for (int c = 0; c < NCH; c++) {
        if (c <= NCH - 3) cp_wait<2>();
        else if (c == NCH - 2) cp_wait<1>();
        else cp_wait<0>();
        __syncthreads();

        const int s = c % NS;
        const uint32_t stA = smem + (uint32_t)s * STAGEB;
        const uint32_t stB = stA + TILEB;
        const uint32_t aAddr = stA + aLaneRow * ROWB + aLaneOff;
        const uint32_t bAddr = stB + bLaneRow * ROWB + bLaneOff;

#pragma unroll
        for (int ks = 0; ks < 2; ks++) {
            uint32_t a[4][4];
#pragma unroll
            for (int mf = 0; mf < 4; mf++)
                ldsm4(a[mf], aAddr + mf * 16 * ROWB + ks * 32);
            uint32_t b[2][4];
#pragma unroll
            for (int bp = 0; bp < 2; bp++)
                ldsm4(b[bp], bAddr + bp * 16 * ROWB + ks * 32);
#pragma unroll
            for (int mf = 0; mf < 4; mf++)
#pragma unroll
                for (int nf = 0; nf < 4; nf++) {
                    const uint32_t* bf = &b[nf >> 1][(nf & 1) * 2];
                    mma16816(acc[mf][nf], a[mf], bf);
                }
        }
        __syncthreads();
        if (c + 3 < NCH) load_chunk(c + 3);
    }

    // Epilogue
    const int gr = lane >> 2, tc = lane & 3;
#pragma unroll
    for (int mf = 0; mf < 4; mf++) {
#pragma unroll
        for (int nf = 0; nf < 4; nf++) {
            int row = m0 + wm * 64 + mf * 16 + gr;
            int coll = wn * 32 + nf * 8 + tc * 2;
            int col = n0 + coll;
            float b0 = bias_s[coll], b1 = bias_s[coll + 1];
            float v0 = acc[mf][nf][0] + b0, v1 = acc[mf][nf][1] + b1;
            float v2 = acc[mf][nf][2] + b0, v3 = acc[mf][nf][3] + b1;
            if (WriteSplit) {
                store_split2(Ch, Cl, (size_t)row * D + col, v0, v1);
                store_split2(Ch, Cl, (size_t)(row + 8) * D + col, v2, v3);
            } else {
                float2 p0; p0.x = v0; p0.y = v1;
                float2 p1; p1.x = v2; p1.y = v3;
                *(float2*)(Cf + (size_t)row * D + col) = p0;
                *(float2*)(Cf + (size_t)(row + 8) * D + col) = p1;
            }
        }
    }
}

__global__ __launch_bounds__(256) void gemm_qkv(const float* __restrict__ bq,
                                                const float* __restrict__ bkv)
{
    const int z = blockIdx.z;
    const __nv_bfloat16* Ah = (z == 0) ? g_xqh : (z == 1) ? g_xkh : g_xvh;
    const __nv_bfloat16* Al = (z == 0) ? g_xql : (z == 1) ? g_xkl : g_xvl;
    const __nv_bfloat16* Bh = (z == 0) ? g_wqh : g_wkh;
    const __nv_bfloat16* Bl = (z == 0) ? g_wql : g_wkl;
    const float* bias = (z == 0) ? bq : bkv;
    __nv_bfloat16* Ch = (z == 0) ? g_qh : (z == 1) ? g_kh : g_vh;
    __nv_bfloat16* Cl = (z == 0) ? g_ql : (z == 1) ? g_kl : g_vl;
    gemm_body<true>(Ah, Al, Bh, Bl, bias, nullptr, Ch, Cl);
}

__global__ __launch_bounds__(256) void gemm_out(const float* __restrict__ bo,
                                                float* __restrict__ out)
{
    gemm_body<false>(g_oh, g_ol, g_woh, g_wol, bo, out, nullptr, nullptr);
}

// ============================================================================
// Fused per-patch attention (fp32 SIMT over reconstructed hi+lo inputs).
// ============================================================================
__global__ __launch_bounds__(256) void attn_kernel()
{
    const int patch = blockIdx.x;
    const size_t base = (size_t)patch * L * D;

    __shared__ __align__(16) float qs[64 * 49];
    __shared__ __align__(16) float ks[64 * 49];
    __shared__ float Ss[48][49];

    const int tid = threadIdx.x;
    const int tx = tid & 15;
    const int ty = tid >> 4;

    float s[3][3];
#pragma unroll
    for (int i = 0; i < 3; i++)
#pragma unroll
        for (int j = 0; j < 3; j++) s[i][j] = 0.0f;

    for (int d0 = 0; d0 < D; d0 += 64) {
#pragma unroll
        for (int r = 0; r < 3; r++) {
            int id = tid + r * 256;
            int row = id >> 4;
            int c4 = id & 15;
            size_t gi = base + (size_t)row * D + d0 + c4 * 4;
            float4 vq = ld4_split(g_qh, g_ql, gi);
            float4 vk = ld4_split(g_kh, g_kl, gi);
            qs[(c4 * 4 + 0) * 49 + row] = vq.x;
            qs[(c4 * 4 + 1) * 49 + row] = vq.y;
            qs[(c4 * 4 + 2) * 49 + row] = vq.z;
            qs[(c4 * 4 + 3) * 49 + row] = vq.w;
            ks[(c4 * 4 + 0) * 49 + row] = vk.x;
            ks[(c4 * 4 + 1) * 49 + row] = vk.y;
            ks[(c4 * 4 + 2) * 49 + row] = vk.z;
            ks[(c4 * 4 + 3) * 49 + row] = vk.w;
        }
        __syncthreads();
#pragma unroll 4
        for (int kk = 0; kk < 64; kk++) {
            float a0 = qs[kk * 49 + ty * 3 + 0];
            float a1 = qs[kk * 49 + ty * 3 + 1];
            float a2 = qs[kk * 49 + ty * 3 + 2];
            float b0 = ks[kk * 49 + tx * 3 + 0];
            float b1 = ks[kk * 49 + tx * 3 + 1];
            float b2 = ks[kk * 49 + tx * 3 + 2];
            s[0][0] = fmaf(a0, b0, s[0][0]);
            s[0][1] = fmaf(a0, b1, s[0][1]);
            s[0][2] = fmaf(a0, b2, s[0][2]);
            s[1][0] = fmaf(a1, b0, s[1][0]);
            s[1][1] = fmaf(a1, b1, s[1][1]);
            s[1][2] = fmaf(a1, b2, s[1][2]);
            s[2][0] = fmaf(a2, b0, s[2][0]);
            s[2][1] = fmaf(a2, b1, s[2][1]);
            s[2][2] = fmaf(a2, b2, s[2][2]);
        }
        __syncthreads();
    }

    const float scale = 0.044194173824159216f;   // 512^-0.5
#pragma unroll
    for (int i = 0; i < 3; i++)
#pragma unroll
        for (int j = 0; j < 3; j++) {
            int row = ty * 3 + i;
            int col = tx * 3 + j;
            Ss[row][col] = (row == col) ? -INFINITY : s[i][j] * scale;
        }
    __syncthreads();

    if (tid < 48) {
        float m = -INFINITY;
#pragma unroll
        for (int c = 0; c < 48; c++) m = fmaxf(m, Ss[tid][c]);
        float sum = 0.0f;
#pragma unroll
        for (int c = 0; c < 48; c++) {
            float e = __expf(Ss[tid][c] - m);
            Ss[tid][c] = e;
            sum += e;
        }
        float inv = 1.0f / sum;
#pragma unroll
        for (int c = 0; c < 48; c++) Ss[tid][c] *= inv;
    }
    __syncthreads();

    float* vs = qs;
    const int dcol = tid & 63;
    const int lg = tid >> 6;
    for (int d0 = 0; d0 < D; d0 += 64) {
#pragma unroll
        for (int r = 0; r < 3; r++) {
            int id = tid + r * 256;
            int row = id >> 4;
            int c4 = id & 15;
            size_t gi = base + (size_t)row * D + d0 + c4 * 4;
            *(float4*)&vs[row * 64 + c4 * 4] = ld4_split(g_vh, g_vl, gi);
        }
        __syncthreads();
#pragma unroll
        for (int lb = 0; lb < 12; lb++) {
            int l = lb * 4 + lg;
            float accv = 0.0f;
#pragma unroll
            for (int m = 0; m < 48; m++)
                accv = fmaf(Ss[l][m], vs[m * 64 + dcol], accv);
            __nv_bfloat16 hi = __float2bfloat16(accv);
            size_t oi = base + (size_t)l * D + d0 + dcol;
            g_oh[oi] = hi;
            g_ol[oi] = __float2bfloat16(accv - __bfloat162float(hi));
        }
        __syncthreads();
    }
}

// ============================================================================
extern "C" void kernel_launch(void* const* d_in, const int* in_sizes, int n_in,
                              void* d_out, int out_size)
{
    const float* queries = (const float*)d_in[0];
    const float* keys    = (const float*)d_in[1];
    const float* values  = (const float*)d_in[2];
    const float* Wq      = (const float*)d_in[3];
    const float* bq      = (const float*)d_in[4];
    const float* Wkv     = (const float*)d_in[5];
    const float* bkv     = (const float*)d_in[6];
    const float* Wo      = (const float*)d_in[7];
    const float* bo      = (const float*)d_in[8];
    float* out = (float*)d_out;

    cudaFuncSetAttribute(gemm_qkv, cudaFuncAttributeMaxDynamicSharedMemorySize,
                         SMEM_DYN);
    cudaFuncSetAttribute(gemm_out, cudaFuncAttributeMaxDynamicSharedMemorySize,
                         SMEM_DYN);

    conv_inputs<<<(int)(((size_t)MTOT * D / 4) / 256), 256>>>(queries, keys, values);
    conv_weights<<<(D * D / 4) / 256, 256>>>(Wq, Wkv, Wo);

    dim3 gqkv(D / BN, MTOT / BM, 3);
    gemm_qkv<<<gqkv, 256, SMEM_DYN>>>(bq, bkv);

    attn_kernel<<<NPATCH, 256>>>();

    dim3 gout(D / BN, MTOT / BM);
    gemm_out<<<gout, 256, SMEM_DYN>>>(bo, out);
}

// round 4
// speedup vs baseline: 2.0868x; 1.0309x over previous
#include <cuda_runtime.h>
#include <cuda_bf16.h>
#include <math.h>
#include <stdint.h>

// ============================================================================
// Problem constants
// ============================================================================
namespace {
constexpr int D = 512;
constexpr int L = 48;
constexpr int NPATCH = 8 * 7 * 24;     // 1344
constexpr int MTOT = NPATCH * L;       // 64512
constexpr int BM = 128, BN = 128;
constexpr int BK = 32;                 // bf16 elems per k0 chunk
constexpr int NK0 = D / BK;            // 16 chunks
constexpr int NS = 3;                  // pipeline stages
constexpr int ROWB = 80;               // smem row stride bytes (64 data + 16 pad)
constexpr int TILEB = 128 * ROWB;      // 10240 per tile
constexpr int STAGEB = 4 * TILEB;      // Ahi, Alo, Bhi, Blo
constexpr int SMEM_DYN = NS * STAGEB;  // 122880

// attention smem layout (floats)
constexpr int QS_F = 64 * 50;          // 3200
constexpr int SP_F = 48 * 49;          // 2352 per group
constexpr int ATTN_SMEM = (2 * QS_F + 4 * SP_F) * 4;   // 63232 bytes
}

// ============================================================================
// Scratch (__device__ globals; no cudaMalloc allowed)
// ============================================================================
__device__ __nv_bfloat16 g_xqh[(size_t)MTOT * D], g_xql[(size_t)MTOT * D];
__device__ __nv_bfloat16 g_xkh[(size_t)MTOT * D], g_xkl[(size_t)MTOT * D];
__device__ __nv_bfloat16 g_xvh[(size_t)MTOT * D], g_xvl[(size_t)MTOT * D];
__device__ __nv_bfloat16 g_qh[(size_t)MTOT * D],  g_ql[(size_t)MTOT * D];
__device__ __nv_bfloat16 g_kh[(size_t)MTOT * D],  g_kl[(size_t)MTOT * D];
__device__ __nv_bfloat16 g_vh[(size_t)MTOT * D],  g_vl[(size_t)MTOT * D];
__device__ __nv_bfloat16 g_oh[(size_t)MTOT * D],  g_ol[(size_t)MTOT * D];
__device__ __nv_bfloat16 g_wqh[D * D], g_wql[D * D];
__device__ __nv_bfloat16 g_wkh[D * D], g_wkl[D * D];
__device__ __nv_bfloat16 g_woh[D * D], g_wol[D * D];

// ============================================================================
// PTX helpers (sm_90-compatible baseline PTX only — NO tcgen05; harness
// compiles PTX for compute_103 without the 'a' suffix)
// ============================================================================
__device__ __forceinline__ uint32_t smem_u32(const void* p) {
    uint32_t a;
    asm("{ .reg .u64 t; cvta.to.shared.u64 t, %1; cvt.u32.u64 %0, t; }"
        : "=r"(a) : "l"(p));
    return a;
}
__device__ __forceinline__ void cp_async16(uint32_t dst, const void* src) {
    asm volatile("cp.async.cg.shared.global [%0], [%1], 16;" :: "r"(dst), "l"(src));
}
__device__ __forceinline__ void cp_commit() {
    asm volatile("cp.async.commit_group;" ::: "memory");
}
template <int N>
__device__ __forceinline__ void cp_wait() {
    asm volatile("cp.async.wait_group %0;" :: "n"(N) : "memory");
}
__device__ __forceinline__ void ldsm4(uint32_t* r, uint32_t addr) {
    asm volatile("ldmatrix.sync.aligned.m8n8.x4.shared.b16 {%0,%1,%2,%3}, [%4];"
                 : "=r"(r[0]), "=r"(r[1]), "=r"(r[2]), "=r"(r[3]) : "r"(addr));
}
__device__ __forceinline__ void mma16816(float* c, const uint32_t* a,
                                         const uint32_t* b) {
    asm volatile(
        "mma.sync.aligned.m16n8k16.row.col.f32.bf16.bf16.f32 "
        "{%0,%1,%2,%3}, {%4,%5,%6,%7}, {%8,%9}, {%0,%1,%2,%3};"
        : "+f"(c[0]), "+f"(c[1]), "+f"(c[2]), "+f"(c[3])
        : "r"(a[0]), "r"(a[1]), "r"(a[2]), "r"(a[3]), "r"(b[0]), "r"(b[1]));
}

// ============================================================================
// fp32 -> bf16 hi/lo split
// ============================================================================
__device__ __forceinline__ void split4(const float4 x, ushort4& h, ushort4& l) {
    float xs[4] = {x.x, x.y, x.z, x.w};
    unsigned short hv[4], lv[4];
#pragma unroll
    for (int j = 0; j < 4; j++) {
        __nv_bfloat16 hh = __float2bfloat16(xs[j]);
        float r = xs[j] - __bfloat162float(hh);
        hv[j] = __bfloat16_as_ushort(hh);
        lv[j] = __bfloat16_as_ushort(__float2bfloat16(r));
    }
    h = make_ushort4(hv[0], hv[1], hv[2], hv[3]);
    l = make_ushort4(lv[0], lv[1], lv[2], lv[3]);
}
__device__ __forceinline__ void store_split2(__nv_bfloat16* H, __nv_bfloat16* L,
                                             size_t idx, float v0, float v1) {
    __nv_bfloat16 h0 = __float2bfloat16(v0);
    __nv_bfloat16 h1 = __float2bfloat16(v1);
    __nv_bfloat162 hh; hh.x = h0; hh.y = h1;
    *(__nv_bfloat162*)(H + idx) = hh;
    __nv_bfloat162 ll;
    ll.x = __float2bfloat16(v0 - __bfloat162float(h0));
    ll.y = __float2bfloat16(v1 - __bfloat162float(h1));
    *(__nv_bfloat162*)(L + idx) = ll;
}
__device__ __forceinline__ float4 ld4_split(const __nv_bfloat16* H,
                                            const __nv_bfloat16* L, size_t idx) {
    ushort4 h = *(const ushort4*)(H + idx);
    ushort4 l = *(const ushort4*)(L + idx);
    float4 r;
    r.x = __bfloat162float(__ushort_as_bfloat16(h.x)) +
          __bfloat162float(__ushort_as_bfloat16(l.x));
    r.y = __bfloat162float(__ushort_as_bfloat16(h.y)) +
          __bfloat162float(__ushort_as_bfloat16(l.y));
    r.z = __bfloat162float(__ushort_as_bfloat16(h.z)) +
          __bfloat162float(__ushort_as_bfloat16(l.z));
    r.w = __bfloat162float(__ushort_as_bfloat16(h.w)) +
          __bfloat162float(__ushort_as_bfloat16(l.w));
    return r;
}

__global__ __launch_bounds__(256) void conv_inputs(
    const float* __restrict__ q, const float* __restrict__ k,
    const float* __restrict__ v)
{
    size_t i4 = (size_t)blockIdx.x * 256 + threadIdx.x;
    size_t idx = i4 * 4;
    ushort4 h, l;
    split4(((const float4*)q)[i4], h, l);
    *(ushort4*)(g_xqh + idx) = h; *(ushort4*)(g_xql + idx) = l;
    split4(((const float4*)k)[i4], h, l);
    *(ushort4*)(g_xkh + idx) = h; *(ushort4*)(g_xkl + idx) = l;
    split4(((const float4*)v)[i4], h, l);
    *(ushort4*)(g_xvh + idx) = h; *(ushort4*)(g_xvl + idx) = l;
}

__global__ __launch_bounds__(256) void conv_weights(
    const float* __restrict__ wq, const float* __restrict__ wkv,
    const float* __restrict__ wo)
{
    size_t i4 = (size_t)blockIdx.x * 256 + threadIdx.x;
    size_t idx = i4 * 4;
    ushort4 h, l;
    split4(((const float4*)wq)[i4], h, l);
    *(ushort4*)(g_wqh + idx) = h; *(ushort4*)(g_wql + idx) = l;
    split4(((const float4*)wkv)[i4], h, l);
    *(ushort4*)(g_wkh + idx) = h; *(ushort4*)(g_wkl + idx) = l;
    split4(((const float4*)wo)[i4], h, l);
    *(ushort4*)(g_woh + idx) = h; *(ushort4*)(g_wol + idx) = l;
}

// ============================================================================
// HMMA GEMM with DEDUPED tile loads: per k0, load Ahi/Alo/Bhi/Blo once,
// run 3 split-term MMA passes (AhBh + AhBl + AlBh) from the same stage.
// ============================================================================
template <bool WriteSplit>
__device__ __forceinline__ void gemm_body(
    const __nv_bfloat16* __restrict__ Ahi, const __nv_bfloat16* __restrict__ Alo,
    const __nv_bfloat16* __restrict__ Bhi, const __nv_bfloat16* __restrict__ Blo,
    const float* __restrict__ bias, float* __restrict__ Cf,
    __nv_bfloat16* __restrict__ Ch, __nv_bfloat16* __restrict__ Cl)
{
    extern __shared__ __align__(16) char dsm[];
    const uint32_t smem = smem_u32(dsm);
    __shared__ float bias_s[BN];

    const int tid = threadIdx.x;
    const int wid = tid >> 5, lane = tid & 31;
    const int wm = wid & 1, wn = wid >> 1;           // 2 x 4 warp grid
    const int n0 = blockIdx.x * BN;
    const int m0 = blockIdx.y * BM;

    if (tid < BN) bias_s[tid] = bias[n0 + tid];

    float acc[4][4][4];
#pragma unroll
    for (int i = 0; i < 4; i++)
#pragma unroll
        for (int j = 0; j < 4; j++)
#pragma unroll
            for (int e = 0; e < 4; e++) acc[i][j][e] = 0.0f;

    const int row = tid >> 2;        // 0..63
    const int c16 = tid & 3;

    auto load_chunk = [&](int c) {
        const int s = c % NS;
        const int k0 = c * BK;
        const uint32_t st = smem + (uint32_t)s * STAGEB;
        const __nv_bfloat16* srcs[4] = {Ahi, Alo, Bhi, Blo};
#pragma unroll
        for (int t = 0; t < 4; t++) {
            const int r0 = (t < 2) ? m0 : n0;
#pragma unroll
            for (int r = 0; r < 2; r++) {
                int rr = row + r * 64;
                cp_async16(st + t * TILEB + rr * ROWB + c16 * 16,
                           srcs[t] + (size_t)(r0 + rr) * D + k0 + c16 * 8);
            }
        }
        cp_commit();
    };

    load_chunk(0);
    load_chunk(1);
    load_chunk(2);

    const uint32_t aLaneRow = (uint32_t)(wm * 64 + (lane & 15));
    const uint32_t aLaneOff = (uint32_t)(((lane >> 4) & 1) * 16);
    const uint32_t bLaneRow = (uint32_t)(wn * 32 + ((lane >> 4) & 1) * 8 + (lane & 7));
    const uint32_t bLaneOff = (uint32_t)(((lane >> 3) & 1) * 16);

    for (int c = 0; c < NK0; c++) {
        if (c <= NK0 - 3) cp_wait<2>();
        else if (c == NK0 - 2) cp_wait<1>();
        else cp_wait<0>();
        __syncthreads();

        const int s = c % NS;
        const uint32_t st = smem + (uint32_t)s * STAGEB;
        const uint32_t aAddrH = st + aLaneRow * ROWB + aLaneOff;
        const uint32_t aAddrL = aAddrH + TILEB;
        const uint32_t bAddrH = st + 2 * TILEB + bLaneRow * ROWB + bLaneOff;
        const uint32_t bAddrL = bAddrH + TILEB;

#pragma unroll
        for (int ks = 0; ks < 2; ks++) {
            uint32_t aH[4][4], aL[4][4], bH[2][4], bL[2][4];
#pragma unroll
            for (int mf = 0; mf < 4; mf++) {
                ldsm4(aH[mf], aAddrH + mf * 16 * ROWB + ks * 32);
                ldsm4(aL[mf], aAddrL + mf * 16 * ROWB + ks * 32);
            }
#pragma unroll
            for (int bp = 0; bp < 2; bp++) {
                ldsm4(bH[bp], bAddrH + bp * 16 * ROWB + ks * 32);
                ldsm4(bL[bp], bAddrL + bp * 16 * ROWB + ks * 32);
            }
            // term 1: Ahi * Bhi
#pragma unroll
            for (int mf = 0; mf < 4; mf++)
#pragma unroll
                for (int nf = 0; nf < 4; nf++)
                    mma16816(acc[mf][nf], aH[mf], &bH[nf >> 1][(nf & 1) * 2]);
            // term 2: Ahi * Blo
#pragma unroll
            for (int mf = 0; mf < 4; mf++)
#pragma unroll
                for (int nf = 0; nf < 4; nf++)
                    mma16816(acc[mf][nf], aH[mf], &bL[nf >> 1][(nf & 1) * 2]);
            // term 3: Alo * Bhi
#pragma unroll
            for (int mf = 0; mf < 4; mf++)
#pragma unroll
                for (int nf = 0; nf < 4; nf++)
                    mma16816(acc[mf][nf], aL[mf], &bH[nf >> 1][(nf & 1) * 2]);
        }
        __syncthreads();
        if (c + 3 < NK0) load_chunk(c + 3);
    }

    // Epilogue
    const int gr = lane >> 2, tc = lane & 3;
#pragma unroll
    for (int mf = 0; mf < 4; mf++) {
#pragma unroll
        for (int nf = 0; nf < 4; nf++) {
            int rowo = m0 + wm * 64 + mf * 16 + gr;
            int coll = wn * 32 + nf * 8 + tc * 2;
            int col = n0 + coll;
            float b0 = bias_s[coll], b1 = bias_s[coll + 1];
            float v0 = acc[mf][nf][0] + b0, v1 = acc[mf][nf][1] + b1;
            float v2 = acc[mf][nf][2] + b0, v3 = acc[mf][nf][3] + b1;
            if (WriteSplit) {
                store_split2(Ch, Cl, (size_t)rowo * D + col, v0, v1);
                store_split2(Ch, Cl, (size_t)(rowo + 8) * D + col, v2, v3);
            } else {
                float2 p0; p0.x = v0; p0.y = v1;
                float2 p1; p1.x = v2; p1.y = v3;
                *(float2*)(Cf + (size_t)rowo * D + col) = p0;
                *(float2*)(Cf + (size_t)(rowo + 8) * D + col) = p1;
            }
        }
    }
}

__global__ __launch_bounds__(256) void gemm_qkv(const float* __restrict__ bq,
                                                const float* __restrict__ bkv)
{
    const int z = blockIdx.z;
    const __nv_bfloat16* Ah = (z == 0) ? g_xqh : (z == 1) ? g_xkh : g_xvh;
    const __nv_bfloat16* Al = (z == 0) ? g_xql : (z == 1) ? g_xkl : g_xvl;
    const __nv_bfloat16* Bh = (z == 0) ? g_wqh : g_wkh;
    const __nv_bfloat16* Bl = (z == 0) ? g_wql : g_wkl;
    const float* bias = (z == 0) ? bq : bkv;
    __nv_bfloat16* Ch = (z == 0) ? g_qh : (z == 1) ? g_kh : g_vh;
    __nv_bfloat16* Cl = (z == 0) ? g_ql : (z == 1) ? g_kl : g_vl;
    gemm_body<true>(Ah, Al, Bh, Bl, bias, nullptr, Ch, Cl);
}

__global__ __launch_bounds__(256) void gemm_out(const float* __restrict__ bo,
                                                float* __restrict__ out)
{
    gemm_body<false>(g_oh, g_ol, g_woh, g_wol, bo, out, nullptr, nullptr);
}

// ============================================================================
// Fused per-patch attention.
// Stage 1: 4 k-groups x 64 threads (8x8), 6x6 register tiles, float2 LDS.
// ============================================================================
__global__ __launch_bounds__(256) void attn_kernel()
{
    extern __shared__ __align__(16) float asm_f[];
    float* qs = asm_f;                 // [64][50]
    float* ks = asm_f + QS_F;          // [64][50]
    float* Sp = asm_f + 2 * QS_F;      // [4][48*49]

    const int patch = blockIdx.x;
    const size_t base = (size_t)patch * L * D;

    const int tid = threadIdx.x;
    const int g = tid >> 6;            // k-group 0..3
    const int t64 = tid & 63;
    const int px = t64 & 7;            // 8 col-groups of 6
    const int py = t64 >> 3;           // 8 row-groups of 6
    const int py6 = py * 6, px6 = px * 6;

    float s[6][6];
#pragma unroll
    for (int i = 0; i < 6; i++)
#pragma unroll
        for (int j = 0; j < 6; j++) s[i][j] = 0.0f;

    // ---- Stage 1: S = q k^T over D in chunks of 64 ----
    for (int d0 = 0; d0 < D; d0 += 64) {
#pragma unroll
        for (int r = 0; r < 3; r++) {
            int id = tid + r * 256;
            int rw = id >> 4;          // 0..47
            int c4 = id & 15;
            size_t gi = base + (size_t)rw * D + d0 + c4 * 4;
            float4 vq = ld4_split(g_qh, g_ql, gi);
            float4 vk = ld4_split(g_kh, g_kl, gi);
            qs[(c4 * 4 + 0) * 50 + rw] = vq.x;
            qs[(c4 * 4 + 1) * 50 + rw] = vq.y;
            qs[(c4 * 4 + 2) * 50 + rw] = vq.z;
            qs[(c4 * 4 + 3) * 50 + rw] = vq.w;
            ks[(c4 * 4 + 0) * 50 + rw] = vk.x;
            ks[(c4 * 4 + 1) * 50 + rw] = vk.y;
            ks[(c4 * 4 + 2) * 50 + rw] = vk.z;
            ks[(c4 * 4 + 3) * 50 + rw] = vk.w;
        }
        __syncthreads();

        const int kb0 = g * 16;
#pragma unroll
        for (int kk = 0; kk < 16; kk++) {
            const int kb = (kb0 + kk) * 50;
            float2 a01 = *(const float2*)&qs[kb + py6];
            float2 a23 = *(const float2*)&qs[kb + py6 + 2];
            float2 a45 = *(const float2*)&qs[kb + py6 + 4];
            float2 b01 = *(const float2*)&ks[kb + px6];
            float2 b23 = *(const float2*)&ks[kb + px6 + 2];
            float2 b45 = *(const float2*)&ks[kb + px6 + 4];
            float a6[6] = {a01.x, a01.y, a23.x, a23.y, a45.x, a45.y};
            float b6[6] = {b01.x, b01.y, b23.x, b23.y, b45.x, b45.y};
#pragma unroll
            for (int i = 0; i < 6; i++)
#pragma unroll
                for (int j = 0; j < 6; j++)
                    s[i][j] = fmaf(a6[i], b6[j], s[i][j]);
        }
        __syncthreads();
    }

    // write partials
#pragma unroll
    for (int i = 0; i < 6; i++)
#pragma unroll
        for (int j = 0; j < 6; j++)
            Sp[g * SP_F + (py6 + i) * 49 + px6 + j] = s[i][j];
    __syncthreads();

    // ---- Stage 2: reduce partials, mask + scale, softmax ----
    const float scale = 0.044194173824159216f;   // 512^-0.5
    for (int idx = tid; idx < 48 * 48; idx += 256) {
        int rw = idx / 48, cl = idx % 48;
        int o = rw * 49 + cl;
        float v = Sp[o] + Sp[SP_F + o] + Sp[2 * SP_F + o] + Sp[3 * SP_F + o];
        Sp[o] = (rw == cl) ? -INFINITY : v * scale;
    }
    __syncthreads();

    if (tid < 48) {
        float m = -INFINITY;
#pragma unroll
        for (int c = 0; c < 48; c++) m = fmaxf(m, Sp[tid * 49 + c]);
        float sum = 0.0f;
#pragma unroll
        for (int c = 0; c < 48; c++) {
            float e = __expf(Sp[tid * 49 + c] - m);
            Sp[tid * 49 + c] = e;
            sum += e;
        }
        float inv = 1.0f / sum;
#pragma unroll
        for (int c = 0; c < 48; c++) Sp[tid * 49 + c] *= inv;
    }
    __syncthreads();

    // ---- Stage 3: out = attn @ v ----
    float* vs = qs;   // 48*64 = 3072 <= QS_F
    const int dcol = tid & 63;
    const int lg = tid >> 6;
    for (int d0 = 0; d0 < D; d0 += 64) {
#pragma unroll
        for (int r = 0; r < 3; r++) {
            int id = tid + r * 256;
            int rw = id >> 4;
            int c4 = id & 15;
            size_t gi = base + (size_t)rw * D + d0 + c4 * 4;
            *(float4*)&vs[rw * 64 + c4 * 4] = ld4_split(g_vh, g_vl, gi);
        }
        __syncthreads();
#pragma unroll
        for (int lb = 0; lb < 12; lb++) {
            int l = lb * 4 + lg;
            float accv = 0.0f;
#pragma unroll
            for (int m = 0; m < 48; m++)
                accv = fmaf(Sp[l * 49 + m], vs[m * 64 + dcol], accv);
            __nv_bfloat16 hi = __float2bfloat16(accv);
            size_t oi = base + (size_t)l * D + d0 + dcol;
            g_oh[oi] = hi;
            g_ol[oi] = __float2bfloat16(accv - __bfloat162float(hi));
        }
        __syncthreads();
    }
}

// ============================================================================
extern "C" void kernel_launch(void* const* d_in, const int* in_sizes, int n_in,
                              void* d_out, int out_size)
{
    const float* queries = (const float*)d_in[0];
    const float* keys    = (const float*)d_in[1];
    const float* values  = (const float*)d_in[2];
    const float* Wq      = (const float*)d_in[3];
    const float* bq      = (const float*)d_in[4];
    const float* Wkv     = (const float*)d_in[5];
    const float* bkv     = (const float*)d_in[6];
    const float* Wo      = (const float*)d_in[7];
    const float* bo      = (const float*)d_in[8];
    float* out = (float*)d_out;

    cudaFuncSetAttribute(gemm_qkv, cudaFuncAttributeMaxDynamicSharedMemorySize,
                         SMEM_DYN);
    cudaFuncSetAttribute(gemm_out, cudaFuncAttributeMaxDynamicSharedMemorySize,
                         SMEM_DYN);
    cudaFuncSetAttribute(attn_kernel, cudaFuncAttributeMaxDynamicSharedMemorySize,
                         ATTN_SMEM);

    conv_inputs<<<(int)(((size_t)MTOT * D / 4) / 256), 256>>>(queries, keys, values);
    conv_weights<<<(D * D / 4) / 256, 256>>>(Wq, Wkv, Wo);

    dim3 gqkv(D / BN, MTOT / BM, 3);
    gemm_qkv<<<gqkv, 256, SMEM_DYN>>>(bq, bkv);

    attn_kernel<<<NPATCH, 256, ATTN_SMEM>>>();

    dim3 gout(D / BN, MTOT / BM);
    gemm_out<<<gout, 256, SMEM_DYN>>>(bo, out);
}

// round 5
// speedup vs baseline: 2.3658x; 1.1337x over previous
#include <cuda_runtime.h>
#include <cuda_bf16.h>
#include <math.h>
#include <stdint.h>

// ============================================================================
// Problem constants
// ============================================================================
namespace {
constexpr int D = 512;
constexpr int L = 48;
constexpr int NPATCH = 8 * 7 * 24;     // 1344
constexpr int MTOT = NPATCH * L;       // 64512
constexpr int BM = 256, BN = 128;
constexpr int BK = 32;                 // bf16 elems per k0 chunk
constexpr int NK0 = D / BK;            // 16 chunks
constexpr int NS = 2;                  // pipeline stages
constexpr int ROWB = 80;               // smem row stride bytes (64 data + 16 pad)
constexpr int ATILEB = 256 * ROWB;     // 20480
constexpr int BTILEB = 128 * ROWB;     // 10240
constexpr int STAGEB = 2 * ATILEB + 2 * BTILEB;  // 61440
constexpr int SMEM_DYN = NS * STAGEB;  // 122880

// attention smem layout (floats)
constexpr int QS_F = 64 * 50;          // 3200
constexpr int SP_F = 48 * 49;          // 2352 per group
constexpr int ATTN_SMEM = (2 * QS_F + 4 * SP_F) * 4;   // 63232 bytes
}

// ============================================================================
// Scratch (__device__ globals; no cudaMalloc allowed)
// ============================================================================
__device__ __nv_bfloat16 g_xqh[(size_t)MTOT * D], g_xql[(size_t)MTOT * D];
__device__ __nv_bfloat16 g_xkh[(size_t)MTOT * D], g_xkl[(size_t)MTOT * D];
__device__ __nv_bfloat16 g_xvh[(size_t)MTOT * D], g_xvl[(size_t)MTOT * D];
__device__ __nv_bfloat16 g_qh[(size_t)MTOT * D],  g_ql[(size_t)MTOT * D];
__device__ __nv_bfloat16 g_kh[(size_t)MTOT * D],  g_kl[(size_t)MTOT * D];
__device__ __nv_bfloat16 g_vh[(size_t)MTOT * D],  g_vl[(size_t)MTOT * D];
__device__ __nv_bfloat16 g_oh[(size_t)MTOT * D],  g_ol[(size_t)MTOT * D];
__device__ __nv_bfloat16 g_wqh[D * D], g_wql[D * D];
__device__ __nv_bfloat16 g_wkh[D * D], g_wkl[D * D];
__device__ __nv_bfloat16 g_woh[D * D], g_wol[D * D];

// ============================================================================
// PTX helpers (sm_90-compatible baseline PTX only — NO tcgen05; harness
// compiles PTX for compute_103 without the 'a' suffix)
// ============================================================================
__device__ __forceinline__ uint32_t smem_u32(const void* p) {
    uint32_t a;
    asm("{ .reg .u64 t; cvta.to.shared.u64 t, %1; cvt.u32.u64 %0, t; }"
        : "=r"(a) : "l"(p));
    return a;
}
__device__ __forceinline__ void cp_async16(uint32_t dst, const void* src) {
    asm volatile("cp.async.cg.shared.global [%0], [%1], 16;" :: "r"(dst), "l"(src));
}
__device__ __forceinline__ void cp_commit() {
    asm volatile("cp.async.commit_group;" ::: "memory");
}
template <int N>
__device__ __forceinline__ void cp_wait() {
    asm volatile("cp.async.wait_group %0;" :: "n"(N) : "memory");
}
__device__ __forceinline__ void ldsm4(uint32_t* r, uint32_t addr) {
    asm volatile("ldmatrix.sync.aligned.m8n8.x4.shared.b16 {%0,%1,%2,%3}, [%4];"
                 : "=r"(r[0]), "=r"(r[1]), "=r"(r[2]), "=r"(r[3]) : "r"(addr));
}
__device__ __forceinline__ void mma16816(float* c, const uint32_t* a,
                                         const uint32_t* b) {
    asm volatile(
        "mma.sync.aligned.m16n8k16.row.col.f32.bf16.bf16.f32 "
        "{%0,%1,%2,%3}, {%4,%5,%6,%7}, {%8,%9}, {%0,%1,%2,%3};"
        : "+f"(c[0]), "+f"(c[1]), "+f"(c[2]), "+f"(c[3])
        : "r"(a[0]), "r"(a[1]), "r"(a[2]), "r"(a[3]), "r"(b[0]), "r"(b[1]));
}

// ============================================================================
// fp32 -> bf16 hi/lo split
// ============================================================================
__device__ __forceinline__ void split4(const float4 x, ushort4& h, ushort4& l) {
    float xs[4] = {x.x, x.y, x.z, x.w};
    unsigned short hv[4], lv[4];
#pragma unroll
    for (int j = 0; j < 4; j++) {
        __nv_bfloat16 hh = __float2bfloat16(xs[j]);
        float r = xs[j] - __bfloat162float(hh);
        hv[j] = __bfloat16_as_ushort(hh);
        lv[j] = __bfloat16_as_ushort(__float2bfloat16(r));
    }
    h = make_ushort4(hv[0], hv[1], hv[2], hv[3]);
    l = make_ushort4(lv[0], lv[1], lv[2], lv[3]);
}
__device__ __forceinline__ void store_split2(__nv_bfloat16* H, __nv_bfloat16* L,
                                             size_t idx, float v0, float v1) {
    __nv_bfloat16 h0 = __float2bfloat16(v0);
    __nv_bfloat16 h1 = __float2bfloat16(v1);
    __nv_bfloat162 hh; hh.x = h0; hh.y = h1;
    *(__nv_bfloat162*)(H + idx) = hh;
    __nv_bfloat162 ll;
    ll.x = __float2bfloat16(v0 - __bfloat162float(h0));
    ll.y = __float2bfloat16(v1 - __bfloat162float(h1));
    *(__nv_bfloat162*)(L + idx) = ll;
}
__device__ __forceinline__ float4 ld4_split(const __nv_bfloat16* H,
                                            const __nv_bfloat16* L, size_t idx) {
    ushort4 h = *(const ushort4*)(H + idx);
    ushort4 l = *(const ushort4*)(L + idx);
    float4 r;
    r.x = __bfloat162float(__ushort_as_bfloat16(h.x)) +
          __bfloat162float(__ushort_as_bfloat16(l.x));
    r.y = __bfloat162float(__ushort_as_bfloat16(h.y)) +
          __bfloat162float(__ushort_as_bfloat16(l.y));
    r.z = __bfloat162float(__ushort_as_bfloat16(h.z)) +
          __bfloat162float(__ushort_as_bfloat16(l.z));
    r.w = __bfloat162float(__ushort_as_bfloat16(h.w)) +
          __bfloat162float(__ushort_as_bfloat16(l.w));
    return r;
}

__global__ __launch_bounds__(256) void conv_inputs(
    const float* __restrict__ q, const float* __restrict__ k,
    const float* __restrict__ v)
{
    size_t i4 = (size_t)blockIdx.x * 256 + threadIdx.x;
    size_t idx = i4 * 4;
    ushort4 h, l;
    split4(((const float4*)q)[i4], h, l);
    *(ushort4*)(g_xqh + idx) = h; *(ushort4*)(g_xql + idx) = l;
    split4(((const float4*)k)[i4], h, l);
    *(ushort4*)(g_xkh + idx) = h; *(ushort4*)(g_xkl + idx) = l;
    split4(((const float4*)v)[i4], h, l);
    *(ushort4*)(g_xvh + idx) = h; *(ushort4*)(g_xvl + idx) = l;
}

__global__ __launch_bounds__(256) void conv_weights(
    const float* __restrict__ wq, const float* __restrict__ wkv,
    const float* __restrict__ wo)
{
    size_t i4 = (size_t)blockIdx.x * 256 + threadIdx.x;
    size_t idx = i4 * 4;
    ushort4 h, l;
    split4(((const float4*)wq)[i4], h, l);
    *(ushort4*)(g_wqh + idx) = h; *(ushort4*)(g_wql + idx) = l;
    split4(((const float4*)wkv)[i4], h, l);
    *(ushort4*)(g_wkh + idx) = h; *(ushort4*)(g_wkl + idx) = l;
    split4(((const float4*)wo)[i4], h, l);
    *(ushort4*)(g_woh + idx) = h; *(ushort4*)(g_wol + idx) = l;
}

// ============================================================================
// HMMA GEMM: BM=256 x BN=128, 512 threads (4x4 warp grid, 64x32 per warp),
// NS=2 pipeline, deduped hi/lo tiles, 3 split-term passes per chunk.
// ============================================================================
template <bool WriteSplit>
__device__ __forceinline__ void gemm_body(
    const __nv_bfloat16* __restrict__ Ahi, const __nv_bfloat16* __restrict__ Alo,
    const __nv_bfloat16* __restrict__ Bhi, const __nv_bfloat16* __restrict__ Blo,
    const float* __restrict__ bias, float* __restrict__ Cf,
    __nv_bfloat16* __restrict__ Ch, __nv_bfloat16* __restrict__ Cl)
{
    extern __shared__ __align__(16) char dsm[];
    const uint32_t smem = smem_u32(dsm);
    __shared__ float bias_s[BN];

    const int tid = threadIdx.x;
    const int wid = tid >> 5, lane = tid & 31;
    const int wm = wid & 3, wn = wid >> 2;           // 4 x 4 warp grid
    const int n0 = blockIdx.x * BN;
    const int m0 = blockIdx.y * BM;

    if (tid < BN) bias_s[tid] = bias[n0 + tid];

    float acc[4][4][4];
#pragma unroll
    for (int i = 0; i < 4; i++)
#pragma unroll
        for (int j = 0; j < 4; j++)
#pragma unroll
            for (int e = 0; e < 4; e++) acc[i][j][e] = 0.0f;

    const int row = tid >> 2;        // 0..127
    const int c16 = tid & 3;

    auto load_chunk = [&](int c) {
        const int s = c % NS;
        const int k0 = c * BK;
        const uint32_t st = smem + (uint32_t)s * STAGEB;
        // A hi/lo: 256 rows each, 2 per thread
#pragma unroll
        for (int r = 0; r < 2; r++) {
            int rr = row + r * 128;
            cp_async16(st + rr * ROWB + c16 * 16,
                       Ahi + (size_t)(m0 + rr) * D + k0 + c16 * 8);
            cp_async16(st + ATILEB + rr * ROWB + c16 * 16,
                       Alo + (size_t)(m0 + rr) * D + k0 + c16 * 8);
        }
        // B hi/lo: 128 rows each, 1 per thread
        cp_async16(st + 2 * ATILEB + row * ROWB + c16 * 16,
                   Bhi + (size_t)(n0 + row) * D + (c * BK) + c16 * 8);
        cp_async16(st + 2 * ATILEB + BTILEB + row * ROWB + c16 * 16,
                   Blo + (size_t)(n0 + row) * D + (c * BK) + c16 * 8);
        cp_commit();
    };

    load_chunk(0);
    load_chunk(1);

    const uint32_t aLaneRow = (uint32_t)(wm * 64 + (lane & 15));
    const uint32_t aLaneOff = (uint32_t)(((lane >> 4) & 1) * 16);
    const uint32_t bLaneRow = (uint32_t)(wn * 32 + ((lane >> 4) & 1) * 8 + (lane & 7));
    const uint32_t bLaneOff = (uint32_t)(((lane >> 3) & 1) * 16);

    for (int c = 0; c < NK0; c++) {
        if (c + 1 < NK0) cp_wait<1>();
        else cp_wait<0>();
        __syncthreads();

        const int s = c % NS;
        const uint32_t st = smem + (uint32_t)s * STAGEB;
        const uint32_t aAddrH = st + aLaneRow * ROWB + aLaneOff;
        const uint32_t aAddrL = aAddrH + ATILEB;
        const uint32_t bAddrH = st + 2 * ATILEB + bLaneRow * ROWB + bLaneOff;
        const uint32_t bAddrL = bAddrH + BTILEB;

#pragma unroll
        for (int ks = 0; ks < 2; ks++) {
            uint32_t aH[4][4], aL[4][4], bH[2][4], bL[2][4];
#pragma unroll
            for (int mf = 0; mf < 4; mf++) {
                ldsm4(aH[mf], aAddrH + mf * 16 * ROWB + ks * 32);
                ldsm4(aL[mf], aAddrL + mf * 16 * ROWB + ks * 32);
            }
#pragma unroll
            for (int bp = 0; bp < 2; bp++) {
                ldsm4(bH[bp], bAddrH + bp * 16 * ROWB + ks * 32);
                ldsm4(bL[bp], bAddrL + bp * 16 * ROWB + ks * 32);
            }
            // term 1: Ahi * Bhi
#pragma unroll
            for (int mf = 0; mf < 4; mf++)
#pragma unroll
                for (int nf = 0; nf < 4; nf++)
                    mma16816(acc[mf][nf], aH[mf], &bH[nf >> 1][(nf & 1) * 2]);
            // term 2: Ahi * Blo
#pragma unroll
            for (int mf = 0; mf < 4; mf++)
#pragma unroll
                for (int nf = 0; nf < 4; nf++)
                    mma16816(acc[mf][nf], aH[mf], &bL[nf >> 1][(nf & 1) * 2]);
            // term 3: Alo * Bhi
#pragma unroll
            for (int mf = 0; mf < 4; mf++)
#pragma unroll
                for (int nf = 0; nf < 4; nf++)
                    mma16816(acc[mf][nf], aL[mf], &bH[nf >> 1][(nf & 1) * 2]);
        }
        __syncthreads();
        if (c + 2 < NK0) load_chunk(c + 2);
    }

    // Epilogue
    const int gr = lane >> 2, tc = lane & 3;
#pragma unroll
    for (int mf = 0; mf < 4; mf++) {
#pragma unroll
        for (int nf = 0; nf < 4; nf++) {
            int rowo = m0 + wm * 64 + mf * 16 + gr;
            int coll = wn * 32 + nf * 8 + tc * 2;
            int col = n0 + coll;
            float b0 = bias_s[coll], b1 = bias_s[coll + 1];
            float v0 = acc[mf][nf][0] + b0, v1 = acc[mf][nf][1] + b1;
            float v2 = acc[mf][nf][2] + b0, v3 = acc[mf][nf][3] + b1;
            if (WriteSplit) {
                store_split2(Ch, Cl, (size_t)rowo * D + col, v0, v1);
                store_split2(Ch, Cl, (size_t)(rowo + 8) * D + col, v2, v3);
            } else {
                float2 p0; p0.x = v0; p0.y = v1;
                float2 p1; p1.x = v2; p1.y = v3;
                *(float2*)(Cf + (size_t)rowo * D + col) = p0;
                *(float2*)(Cf + (size_t)(rowo + 8) * D + col) = p1;
            }
        }
    }
}

__global__ __launch_bounds__(512) void gemm_qkv(const float* __restrict__ bq,
                                                const float* __restrict__ bkv)
{
    const int z = blockIdx.z;
    const __nv_bfloat16* Ah = (z == 0) ? g_xqh : (z == 1) ? g_xkh : g_xvh;
    const __nv_bfloat16* Al = (z == 0) ? g_xql : (z == 1) ? g_xkl : g_xvl;
    const __nv_bfloat16* Bh = (z == 0) ? g_wqh : g_wkh;
    const __nv_bfloat16* Bl = (z == 0) ? g_wql : g_wkl;
    const float* bias = (z == 0) ? bq : bkv;
    __nv_bfloat16* Ch = (z == 0) ? g_qh : (z == 1) ? g_kh : g_vh;
    __nv_bfloat16* Cl = (z == 0) ? g_ql : (z == 1) ? g_kl : g_vl;
    gemm_body<true>(Ah, Al, Bh, Bl, bias, nullptr, Ch, Cl);
}

__global__ __launch_bounds__(512) void gemm_out(const float* __restrict__ bo,
                                                float* __restrict__ out)
{
    gemm_body<false>(g_oh, g_ol, g_woh, g_wol, bo, out, nullptr, nullptr);
}

// ============================================================================
// Fused per-patch attention.
// Stage 1: 4 k-groups x 64 threads (8x8), 6x6 register tiles.
// Stage 3: 16x16 grid, 3l x 4d register tiles (1 LDS.128 + 3 bcast / 12 FMA).
// ============================================================================
__global__ __launch_bounds__(256) void attn_kernel()
{
    extern __shared__ __align__(16) float asm_f[];
    float* qs = asm_f;                 // [64][50]
    float* ks = asm_f + QS_F;          // [64][50]
    float* Sp = asm_f + 2 * QS_F;      // [4][48*49]

    const int patch = blockIdx.x;
    const size_t base = (size_t)patch * L * D;

    const int tid = threadIdx.x;
    const int g = tid >> 6;            // k-group 0..3
    const int t64 = tid & 63;
    const int px = t64 & 7;            // 8 col-groups of 6
    const int py = t64 >> 3;           // 8 row-groups of 6
    const int py6 = py * 6, px6 = px * 6;

    float s[6][6];
#pragma unroll
    for (int i = 0; i < 6; i++)
#pragma unroll
        for (int j = 0; j < 6; j++) s[i][j] = 0.0f;

    // ---- Stage 1: S = q k^T over D in chunks of 64 ----
    for (int d0 = 0; d0 < D; d0 += 64) {
#pragma unroll
        for (int r = 0; r < 3; r++) {
            int id = tid + r * 256;
            int rw = id >> 4;          // 0..47
            int c4 = id & 15;
            size_t gi = base + (size_t)rw * D + d0 + c4 * 4;
            float4 vq = ld4_split(g_qh, g_ql, gi);
            float4 vk = ld4_split(g_kh, g_kl, gi);
            qs[(c4 * 4 + 0) * 50 + rw] = vq.x;
            qs[(c4 * 4 + 1) * 50 + rw] = vq.y;
            qs[(c4 * 4 + 2) * 50 + rw] = vq.z;
            qs[(c4 * 4 + 3) * 50 + rw] = vq.w;
            ks[(c4 * 4 + 0) * 50 + rw] = vk.x;
            ks[(c4 * 4 + 1) * 50 + rw] = vk.y;
            ks[(c4 * 4 + 2) * 50 + rw] = vk.z;
            ks[(c4 * 4 + 3) * 50 + rw] = vk.w;
        }
        __syncthreads();

        const int kb0 = g * 16;
#pragma unroll
        for (int kk = 0; kk < 16; kk++) {
            const int kb = (kb0 + kk) * 50;
            float2 a01 = *(const float2*)&qs[kb + py6];
            float2 a23 = *(const float2*)&qs[kb + py6 + 2];
            float2 a45 = *(const float2*)&qs[kb + py6 + 4];
            float2 b01 = *(const float2*)&ks[kb + px6];
            float2 b23 = *(const float2*)&ks[kb + px6 + 2];
            float2 b45 = *(const float2*)&ks[kb + px6 + 4];
            float a6[6] = {a01.x, a01.y, a23.x, a23.y, a45.x, a45.y};
            float b6[6] = {b01.x, b01.y, b23.x, b23.y, b45.x, b45.y};
#pragma unroll
            for (int i = 0; i < 6; i++)
#pragma unroll
                for (int j = 0; j < 6; j++)
                    s[i][j] = fmaf(a6[i], b6[j], s[i][j]);
        }
        __syncthreads();
    }

    // write partials
#pragma unroll
    for (int i = 0; i < 6; i++)
#pragma unroll
        for (int j = 0; j < 6; j++)
            Sp[g * SP_F + (py6 + i) * 49 + px6 + j] = s[i][j];
    __syncthreads();

    // ---- Stage 2: reduce partials, mask + scale, softmax ----
    const float scale = 0.044194173824159216f;   // 512^-0.5
    for (int idx = tid; idx < 48 * 48; idx += 256) {
        int rw = idx / 48, cl = idx % 48;
        int o = rw * 49 + cl;
        float v = Sp[o] + Sp[SP_F + o] + Sp[2 * SP_F + o] + Sp[3 * SP_F + o];
        Sp[o] = (rw == cl) ? -INFINITY : v * scale;
    }
    __syncthreads();

    if (tid < 48) {
        float m = -INFINITY;
#pragma unroll
        for (int c = 0; c < 48; c++) m = fmaxf(m, Sp[tid * 49 + c]);
        float sum = 0.0f;
#pragma unroll
        for (int c = 0; c < 48; c++) {
            float e = __expf(Sp[tid * 49 + c] - m);
            Sp[tid * 49 + c] = e;
            sum += e;
        }
        float inv = 1.0f / sum;
#pragma unroll
        for (int c = 0; c < 48; c++) Sp[tid * 49 + c] *= inv;
    }
    __syncthreads();

    // ---- Stage 3: out = attn @ v, 3l x 4d register tiles ----
    float* vs = qs;   // 48*64 = 3072 <= QS_F
    const int dg = tid & 15;           // 16 dgroups x 4 cols
    const int lg = tid >> 4;           // 16 lgroups x 3 l
    for (int d0 = 0; d0 < D; d0 += 64) {
#pragma unroll
        for (int r = 0; r < 3; r++) {
            int id = tid + r * 256;
            int rw = id >> 4;
            int c4 = id & 15;
            size_t gi = base + (size_t)rw * D + d0 + c4 * 4;
            *(float4*)&vs[rw * 64 + c4 * 4] = ld4_split(g_vh, g_vl, gi);
        }
        __syncthreads();

        float acc3[3][4];
#pragma unroll
        for (int i = 0; i < 3; i++)
#pragma unroll
            for (int j = 0; j < 4; j++) acc3[i][j] = 0.0f;

#pragma unroll 8
        for (int m = 0; m < 48; m++) {
            float4 vv = *(const float4*)&vs[m * 64 + dg * 4];
#pragma unroll
            for (int i = 0; i < 3; i++) {
                float p = Sp[(lg * 3 + i) * 49 + m];
                acc3[i][0] = fmaf(p, vv.x, acc3[i][0]);
                acc3[i][1] = fmaf(p, vv.y, acc3[i][1]);
                acc3[i][2] = fmaf(p, vv.z, acc3[i][2]);
                acc3[i][3] = fmaf(p, vv.w, acc3[i][3]);
            }
        }

#pragma unroll
        for (int i = 0; i < 3; i++) {
            int l = lg * 3 + i;
            size_t oi = base + (size_t)l * D + d0 + dg * 4;
            unsigned short hv[4], lv[4];
#pragma unroll
            for (int j = 0; j < 4; j++) {
                __nv_bfloat16 hh = __float2bfloat16(acc3[i][j]);
                hv[j] = __bfloat16_as_ushort(hh);
                lv[j] = __bfloat16_as_ushort(
                    __float2bfloat16(acc3[i][j] - __bfloat162float(hh)));
            }
            *(ushort4*)(g_oh + oi) = make_ushort4(hv[0], hv[1], hv[2], hv[3]);
            *(ushort4*)(g_ol + oi) = make_ushort4(lv[0], lv[1], lv[2], lv[3]);
        }
        __syncthreads();
    }
}

// ============================================================================
extern "C" void kernel_launch(void* const* d_in, const int* in_sizes, int n_in,
                              void* d_out, int out_size)
{
    const float* queries = (const float*)d_in[0];
    const float* keys    = (const float*)d_in[1];
    const float* values  = (const float*)d_in[2];
    const float* Wq      = (const float*)d_in[3];
    const float* bq      = (const float*)d_in[4];
    const float* Wkv     = (const float*)d_in[5];
    const float* bkv     = (const float*)d_in[6];
    const float* Wo      = (const float*)d_in[7];
    const float* bo      = (const float*)d_in[8];
    float* out = (float*)d_out;

    cudaFuncSetAttribute(gemm_qkv, cudaFuncAttributeMaxDynamicSharedMemorySize,
                         SMEM_DYN);
    cudaFuncSetAttribute(gemm_out, cudaFuncAttributeMaxDynamicSharedMemorySize,
                         SMEM_DYN);
    cudaFuncSetAttribute(attn_kernel, cudaFuncAttributeMaxDynamicSharedMemorySize,
                         ATTN_SMEM);

    conv_inputs<<<(int)(((size_t)MTOT * D / 4) / 256), 256>>>(queries, keys, values);
    conv_weights<<<(D * D / 4) / 256, 256>>>(Wq, Wkv, Wo);

    dim3 gqkv(D / BN, MTOT / BM, 3);
    gemm_qkv<<<gqkv, 512, SMEM_DYN>>>(bq, bkv);

    attn_kernel<<<NPATCH, 256, ATTN_SMEM>>>();

    dim3 gout(D / BN, MTOT / BM);
    gemm_out<<<gout, 512, SMEM_DYN>>>(bo, out);
}

// round 6
// speedup vs baseline: 3.2610x; 1.3784x over previous
#include <cuda_runtime.h>
#include <cuda_bf16.h>
#include <cuda_fp16.h>
#include <math.h>
#include <stdint.h>

// ============================================================================
// Problem constants
// ============================================================================
namespace {
constexpr int D = 512;
constexpr int L = 48;
constexpr int NPATCH = 8 * 7 * 24;     // 1344
constexpr int MTOT = NPATCH * L;       // 64512
constexpr int BM = 256, BN = 128;
constexpr int BK = 32;                 // fp16 elems per k0 chunk
constexpr int NK0 = D / BK;            // 16 chunks
constexpr int NS = 3;                  // pipeline stages
constexpr int ROWB = 80;               // smem row stride bytes (64 data + 16 pad)
constexpr int ATILEB = 256 * ROWB;     // 20480
constexpr int BTILEB = 128 * ROWB;     // 10240
constexpr int STAGEB = ATILEB + 2 * BTILEB;      // 40960 (A, Bh, Bl)
constexpr int SMEM_DYN = NS * STAGEB;  // 122880

// attention smem layout (floats)
constexpr int QS_F = 64 * 50;          // 3200
constexpr int SP_F = 48 * 49;          // 2352 per group
constexpr int ATTN_SMEM = (2 * QS_F + 4 * SP_F) * 4;   // 63232 bytes
}

// ============================================================================
// Scratch (__device__ globals; no cudaMalloc allowed)
// ============================================================================
__device__ __half g_xq[(size_t)MTOT * D];   // inputs rounded to fp16
__device__ __half g_xk[(size_t)MTOT * D];
__device__ __half g_xv[(size_t)MTOT * D];
__device__ float  g_q[(size_t)MTOT * D];    // projections (fp32)
__device__ float  g_k[(size_t)MTOT * D];
__device__ float  g_v[(size_t)MTOT * D];
__device__ __half g_xo[(size_t)MTOT * D];   // attention out, fp16
__device__ __half g_wqh[D * D], g_wql[D * D];   // weights split hi/lo fp16
__device__ __half g_wkh[D * D], g_wkl[D * D];
__device__ __half g_woh[D * D], g_wol[D * D];

// ============================================================================
// PTX helpers (sm_90-compatible baseline PTX only — NO tcgen05; harness
// compiles PTX for compute_103 without the 'a' suffix)
// ============================================================================
__device__ __forceinline__ uint32_t smem_u32(const void* p) {
    uint32_t a;
    asm("{ .reg .u64 t; cvta.to.shared.u64 t, %1; cvt.u32.u64 %0, t; }"
        : "=r"(a) : "l"(p));
    return a;
}
__device__ __forceinline__ void cp_async16(uint32_t dst, const void* src) {
    asm volatile("cp.async.cg.shared.global [%0], [%1], 16;" :: "r"(dst), "l"(src));
}
__device__ __forceinline__ void cp_commit() {
    asm volatile("cp.async.commit_group;" ::: "memory");
}
template <int N>
__device__ __forceinline__ void cp_wait() {
    asm volatile("cp.async.wait_group %0;" :: "n"(N) : "memory");
}
__device__ __forceinline__ void ldsm4(uint32_t* r, uint32_t addr) {
    asm volatile("ldmatrix.sync.aligned.m8n8.x4.shared.b16 {%0,%1,%2,%3}, [%4];"
                 : "=r"(r[0]), "=r"(r[1]), "=r"(r[2]), "=r"(r[3]) : "r"(addr));
}
__device__ __forceinline__ void mma16816(float* c, const uint32_t* a,
                                         const uint32_t* b) {
    asm volatile(
        "mma.sync.aligned.m16n8k16.row.col.f32.f16.f16.f32 "
        "{%0,%1,%2,%3}, {%4,%5,%6,%7}, {%8,%9}, {%0,%1,%2,%3};"
        : "+f"(c[0]), "+f"(c[1]), "+f"(c[2]), "+f"(c[3])
        : "r"(a[0]), "r"(a[1]), "r"(a[2]), "r"(a[3]), "r"(b[0]), "r"(b[1]));
}

// ============================================================================
// conversions
// ============================================================================
__global__ __launch_bounds__(256) void conv_inputs(
    const float* __restrict__ q, const float* __restrict__ k,
    const float* __restrict__ v)
{
    size_t i4 = (size_t)blockIdx.x * 256 + threadIdx.x;
    size_t idx = i4 * 4;
    float4 a = ((const float4*)q)[i4];
    float4 b = ((const float4*)k)[i4];
    float4 c = ((const float4*)v)[i4];
    ushort4 ra, rb, rc;
    ra.x = __half_as_ushort(__float2half(a.x));
    ra.y = __half_as_ushort(__float2half(a.y));
    ra.z = __half_as_ushort(__float2half(a.z));
    ra.w = __half_as_ushort(__float2half(a.w));
    rb.x = __half_as_ushort(__float2half(b.x));
    rb.y = __half_as_ushort(__float2half(b.y));
    rb.z = __half_as_ushort(__float2half(b.z));
    rb.w = __half_as_ushort(__float2half(b.w));
    rc.x = __half_as_ushort(__float2half(c.x));
    rc.y = __half_as_ushort(__float2half(c.y));
    rc.z = __half_as_ushort(__float2half(c.z));
    rc.w = __half_as_ushort(__float2half(c.w));
    *(ushort4*)(g_xq + idx) = ra;
    *(ushort4*)(g_xk + idx) = rb;
    *(ushort4*)(g_xv + idx) = rc;
}

__device__ __forceinline__ void splitw4(const float4 x, ushort4& h, ushort4& l) {
    float xs[4] = {x.x, x.y, x.z, x.w};
    unsigned short hv[4], lv[4];
#pragma unroll
    for (int j = 0; j < 4; j++) {
        __half hh = __float2half(xs[j]);
        float r = xs[j] - __half2float(hh);
        hv[j] = __half_as_ushort(hh);
        lv[j] = __half_as_ushort(__float2half(r));
    }
    h = make_ushort4(hv[0], hv[1], hv[2], hv[3]);
    l = make_ushort4(lv[0], lv[1], lv[2], lv[3]);
}

__global__ __launch_bounds__(256) void conv_weights(
    const float* __restrict__ wq, const float* __restrict__ wkv,
    const float* __restrict__ wo)
{
    size_t i4 = (size_t)blockIdx.x * 256 + threadIdx.x;
    size_t idx = i4 * 4;
    ushort4 h, l;
    splitw4(((const float4*)wq)[i4], h, l);
    *(ushort4*)(g_wqh + idx) = h; *(ushort4*)(g_wql + idx) = l;
    splitw4(((const float4*)wkv)[i4], h, l);
    *(ushort4*)(g_wkh + idx) = h; *(ushort4*)(g_wkl + idx) = l;
    splitw4(((const float4*)wo)[i4], h, l);
    *(ushort4*)(g_woh + idx) = h; *(ushort4*)(g_wol + idx) = l;
}

// ============================================================================
// HMMA GEMM (fp16 2-term): C[m][n] = sum_d A[m][d]*(Wh+Wl)[n][d] + bias[n]
// BM=256 x BN=128, 512 threads (4x4 warp grid, 64x32 per warp), NS=3.
// ============================================================================
__device__ __forceinline__ void gemm_body(
    const __half* __restrict__ A, const __half* __restrict__ Bh,
    const __half* __restrict__ Bl, const float* __restrict__ bias,
    float* __restrict__ Cf)
{
    extern __shared__ __align__(16) char dsm[];
    const uint32_t smem = smem_u32(dsm);
    __shared__ float bias_s[BN];

    const int tid = threadIdx.x;
    const int wid = tid >> 5, lane = tid & 31;
    const int wm = wid & 3, wn = wid >> 2;           // 4 x 4 warp grid
    const int n0 = blockIdx.x * BN;
    const int m0 = blockIdx.y * BM;

    if (tid < BN) bias_s[tid] = bias[n0 + tid];

    float acc[4][4][4];
#pragma unroll
    for (int i = 0; i < 4; i++)
#pragma unroll
        for (int j = 0; j < 4; j++)
#pragma unroll
            for (int e = 0; e < 4; e++) acc[i][j][e] = 0.0f;

    const int row = tid >> 2;        // 0..127
    const int c16 = tid & 3;

    auto load_chunk = [&](int c) {
        const int s = c % NS;
        const int k0 = c * BK;
        const uint32_t st = smem + (uint32_t)s * STAGEB;
        // A: 256 rows, 2 per thread
#pragma unroll
        for (int r = 0; r < 2; r++) {
            int rr = row + r * 128;
            cp_async16(st + rr * ROWB + c16 * 16,
                       A + (size_t)(m0 + rr) * D + k0 + c16 * 8);
        }
        // B hi/lo: 128 rows each, 1 per thread
        cp_async16(st + ATILEB + row * ROWB + c16 * 16,
                   Bh + (size_t)(n0 + row) * D + k0 + c16 * 8);
        cp_async16(st + ATILEB + BTILEB + row * ROWB + c16 * 16,
                   Bl + (size_t)(n0 + row) * D + k0 + c16 * 8);
        cp_commit();
    };

    load_chunk(0);
    load_chunk(1);
    load_chunk(2);

    const uint32_t aLaneRow = (uint32_t)(wm * 64 + (lane & 15));
    const uint32_t aLaneOff = (uint32_t)(((lane >> 4) & 1) * 16);
    const uint32_t bLaneRow = (uint32_t)(wn * 32 + ((lane >> 4) & 1) * 8 + (lane & 7));
    const uint32_t bLaneOff = (uint32_t)(((lane >> 3) & 1) * 16);

    for (int c = 0; c < NK0; c++) {
        if (c <= NK0 - 3) cp_wait<2>();
        else if (c == NK0 - 2) cp_wait<1>();
        else cp_wait<0>();
        __syncthreads();

        const int s = c % NS;
        const uint32_t st = smem + (uint32_t)s * STAGEB;
        const uint32_t aAddr = st + aLaneRow * ROWB + aLaneOff;
        const uint32_t bAddrH = st + ATILEB + bLaneRow * ROWB + bLaneOff;
        const uint32_t bAddrL = bAddrH + BTILEB;

#pragma unroll
        for (int ks = 0; ks < 2; ks++) {
            uint32_t a[4][4], bH[2][4], bL[2][4];
#pragma unroll
            for (int mf = 0; mf < 4; mf++)
                ldsm4(a[mf], aAddr + mf * 16 * ROWB + ks * 32);
#pragma unroll
            for (int bp = 0; bp < 2; bp++) {
                ldsm4(bH[bp], bAddrH + bp * 16 * ROWB + ks * 32);
                ldsm4(bL[bp], bAddrL + bp * 16 * ROWB + ks * 32);
            }
            // term 1: A * Bh
#pragma unroll
            for (int mf = 0; mf < 4; mf++)
#pragma unroll
                for (int nf = 0; nf < 4; nf++)
                    mma16816(acc[mf][nf], a[mf], &bH[nf >> 1][(nf & 1) * 2]);
            // term 2: A * Bl
#pragma unroll
            for (int mf = 0; mf < 4; mf++)
#pragma unroll
                for (int nf = 0; nf < 4; nf++)
                    mma16816(acc[mf][nf], a[mf], &bL[nf >> 1][(nf & 1) * 2]);
        }
        __syncthreads();
        if (c + 3 < NK0) load_chunk(c + 3);
    }

    // Epilogue (fp32 output)
    const int gr = lane >> 2, tc = lane & 3;
#pragma unroll
    for (int mf = 0; mf < 4; mf++) {
#pragma unroll
        for (int nf = 0; nf < 4; nf++) {
            int rowo = m0 + wm * 64 + mf * 16 + gr;
            int coll = wn * 32 + nf * 8 + tc * 2;
            int col = n0 + coll;
            float b0 = bias_s[coll], b1 = bias_s[coll + 1];
            float2 p0; p0.x = acc[mf][nf][0] + b0; p0.y = acc[mf][nf][1] + b1;
            float2 p1; p1.x = acc[mf][nf][2] + b0; p1.y = acc[mf][nf][3] + b1;
            *(float2*)(Cf + (size_t)rowo * D + col) = p0;
            *(float2*)(Cf + (size_t)(rowo + 8) * D + col) = p1;
        }
    }
}

__global__ __launch_bounds__(512) void gemm_qkv(const float* __restrict__ bq,
                                                const float* __restrict__ bkv)
{
    const int z = blockIdx.z;
    const __half* A  = (z == 0) ? g_xq : (z == 1) ? g_xk : g_xv;
    const __half* Bh = (z == 0) ? g_wqh : g_wkh;
    const __half* Bl = (z == 0) ? g_wql : g_wkl;
    const float* bias = (z == 0) ? bq : bkv;
    float* C = (z == 0) ? g_q : (z == 1) ? g_k : g_v;
    gemm_body(A, Bh, Bl, bias, C);
}

__global__ __launch_bounds__(512) void gemm_out(const float* __restrict__ bo,
                                                float* __restrict__ out)
{
    gemm_body(g_xo, g_woh, g_wol, bo, out);
}

// ============================================================================
// Fused per-patch attention (fp32 in, fp16 out).
// Stage 1: 4 k-groups x 64 threads (8x8), 6x6 register tiles.
// Stage 3: 16x16 grid, 3l x 4d register tiles.
// ============================================================================
__global__ __launch_bounds__(256) void attn_kernel()
{
    extern __shared__ __align__(16) float asm_f[];
    float* qs = asm_f;                 // [64][50]
    float* ks = asm_f + QS_F;          // [64][50]
    float* Sp = asm_f + 2 * QS_F;      // [4][48*49]

    const int patch = blockIdx.x;
    const size_t base = (size_t)patch * L * D;
    const float* q = g_q + base;
    const float* k = g_k + base;
    const float* v = g_v + base;

    const int tid = threadIdx.x;
    const int g = tid >> 6;            // k-group 0..3
    const int t64 = tid & 63;
    const int px = t64 & 7;            // 8 col-groups of 6
    const int py = t64 >> 3;           // 8 row-groups of 6
    const int py6 = py * 6, px6 = px * 6;

    float s[6][6];
#pragma unroll
    for (int i = 0; i < 6; i++)
#pragma unroll
        for (int j = 0; j < 6; j++) s[i][j] = 0.0f;

    // ---- Stage 1: S = q k^T over D in chunks of 64 ----
    for (int d0 = 0; d0 < D; d0 += 64) {
#pragma unroll
        for (int r = 0; r < 3; r++) {
            int id = tid + r * 256;
            int rw = id >> 4;          // 0..47
            int c4 = id & 15;
            float4 vq = *(const float4*)(q + (size_t)rw * D + d0 + c4 * 4);
            float4 vk = *(const float4*)(k + (size_t)rw * D + d0 + c4 * 4);
            qs[(c4 * 4 + 0) * 50 + rw] = vq.x;
            qs[(c4 * 4 + 1) * 50 + rw] = vq.y;
            qs[(c4 * 4 + 2) * 50 + rw] = vq.z;
            qs[(c4 * 4 + 3) * 50 + rw] = vq.w;
            ks[(c4 * 4 + 0) * 50 + rw] = vk.x;
            ks[(c4 * 4 + 1) * 50 + rw] = vk.y;
            ks[(c4 * 4 + 2) * 50 + rw] = vk.z;
            ks[(c4 * 4 + 3) * 50 + rw] = vk.w;
        }
        __syncthreads();

        const int kb0 = g * 16;
#pragma unroll
        for (int kk = 0; kk < 16; kk++) {
            const int kb = (kb0 + kk) * 50;
            float2 a01 = *(const float2*)&qs[kb + py6];
            float2 a23 = *(const float2*)&qs[kb + py6 + 2];
            float2 a45 = *(const float2*)&qs[kb + py6 + 4];
            float2 b01 = *(const float2*)&ks[kb + px6];
            float2 b23 = *(const float2*)&ks[kb + px6 + 2];
            float2 b45 = *(const float2*)&ks[kb + px6 + 4];
            float a6[6] = {a01.x, a01.y, a23.x, a23.y, a45.x, a45.y};
            float b6[6] = {b01.x, b01.y, b23.x, b23.y, b45.x, b45.y};
#pragma unroll
            for (int i = 0; i < 6; i++)
#pragma unroll
                for (int j = 0; j < 6; j++)
                    s[i][j] = fmaf(a6[i], b6[j], s[i][j]);
        }
        __syncthreads();
    }

    // write partials
#pragma unroll
    for (int i = 0; i < 6; i++)
#pragma unroll
        for (int j = 0; j < 6; j++)
            Sp[g * SP_F + (py6 + i) * 49 + px6 + j] = s[i][j];
    __syncthreads();

    // ---- Stage 2: reduce partials, mask + scale, softmax ----
    const float scale = 0.044194173824159216f;   // 512^-0.5
    for (int idx = tid; idx < 48 * 48; idx += 256) {
        int rw = idx / 48, cl = idx % 48;
        int o = rw * 49 + cl;
        float vv = Sp[o] + Sp[SP_F + o] + Sp[2 * SP_F + o] + Sp[3 * SP_F + o];
        Sp[o] = (rw == cl) ? -INFINITY : vv * scale;
    }
    __syncthreads();

    if (tid < 48) {
        float m = -INFINITY;
#pragma unroll
        for (int c = 0; c < 48; c++) m = fmaxf(m, Sp[tid * 49 + c]);
        float sum = 0.0f;
#pragma unroll
        for (int c = 0; c < 48; c++) {
            float e = __expf(Sp[tid * 49 + c] - m);
            Sp[tid * 49 + c] = e;
            sum += e;
        }
        float inv = 1.0f / sum;
#pragma unroll
        for (int c = 0; c < 48; c++) Sp[tid * 49 + c] *= inv;
    }
    __syncthreads();

    // ---- Stage 3: out = attn @ v, 3l x 4d register tiles ----
    float* vs = qs;   // 48*64 = 3072 <= QS_F
    const int dg = tid & 15;           // 16 dgroups x 4 cols
    const int lg = tid >> 4;           // 16 lgroups x 3 l
    for (int d0 = 0; d0 < D; d0 += 64) {
#pragma unroll
        for (int r = 0; r < 3; r++) {
            int id = tid + r * 256;
            int rw = id >> 4;
            int c4 = id & 15;
            *(float4*)&vs[rw * 64 + c4 * 4] =
                *(const float4*)(v + (size_t)rw * D + d0 + c4 * 4);
        }
        __syncthreads();

        float acc3[3][4];
#pragma unroll
        for (int i = 0; i < 3; i++)
#pragma unroll
            for (int j = 0; j < 4; j++) acc3[i][j] = 0.0f;

#pragma unroll 8
        for (int m = 0; m < 48; m++) {
            float4 vv = *(const float4*)&vs[m * 64 + dg * 4];
#pragma unroll
            for (int i = 0; i < 3; i++) {
                float p = Sp[(lg * 3 + i) * 49 + m];
                acc3[i][0] = fmaf(p, vv.x, acc3[i][0]);
                acc3[i][1] = fmaf(p, vv.y, acc3[i][1]);
                acc3[i][2] = fmaf(p, vv.z, acc3[i][2]);
                acc3[i][3] = fmaf(p, vv.w, acc3[i][3]);
            }
        }

#pragma unroll
        for (int i = 0; i < 3; i++) {
            int l = lg * 3 + i;
            size_t oi = base + (size_t)l * D + d0 + dg * 4;
            ushort4 hv;
            hv.x = __half_as_ushort(__float2half(acc3[i][0]));
            hv.y = __half_as_ushort(__float2half(acc3[i][1]));
            hv.z = __half_as_ushort(__float2half(acc3[i][2]));
            hv.w = __half_as_ushort(__float2half(acc3[i][3]));
            *(ushort4*)(g_xo + oi) = hv;
        }
        __syncthreads();
    }
}

// ============================================================================
extern "C" void kernel_launch(void* const* d_in, const int* in_sizes, int n_in,
                              void* d_out, int out_size)
{
    const float* queries = (const float*)d_in[0];
    const float* keys    = (const float*)d_in[1];
    const float* values  = (const float*)d_in[2];
    const float* Wq      = (const float*)d_in[3];
    const float* bq      = (const float*)d_in[4];
    const float* Wkv     = (const float*)d_in[5];
    const float* bkv     = (const float*)d_in[6];
    const float* Wo      = (const float*)d_in[7];
    const float* bo      = (const float*)d_in[8];
    float* out = (float*)d_out;

    cudaFuncSetAttribute(gemm_qkv, cudaFuncAttributeMaxDynamicSharedMemorySize,
                         SMEM_DYN);
    cudaFuncSetAttribute(gemm_out, cudaFuncAttributeMaxDynamicSharedMemorySize,
                         SMEM_DYN);
    cudaFuncSetAttribute(attn_kernel, cudaFuncAttributeMaxDynamicSharedMemorySize,
                         ATTN_SMEM);

    conv_inputs<<<(int)(((size_t)MTOT * D / 4) / 256), 256>>>(queries, keys, values);
    conv_weights<<<(D * D / 4) / 256, 256>>>(Wq, Wkv, Wo);

    dim3 gqkv(D / BN, MTOT / BM, 3);
    gemm_qkv<<<gqkv, 512, SMEM_DYN>>>(bq, bkv);

    attn_kernel<<<NPATCH, 256, ATTN_SMEM>>>();

    dim3 gout(D / BN, MTOT / BM);
    gemm_out<<<gout, 512, SMEM_DYN>>>(bo, out);
}

// round 7
// speedup vs baseline: 4.5300x; 1.3891x over previous
#include <cuda_runtime.h>
#include <cuda_fp16.h>
#include <math.h>
#include <stdint.h>

// ============================================================================
// Problem constants
// ============================================================================
namespace {
constexpr int D = 512;
constexpr int L = 48;
constexpr int NPATCH = 8 * 7 * 24;     // 1344
constexpr int MTOT = NPATCH * L;       // 64512
constexpr int BM = 256, BN = 128;
constexpr int BK = 32;                 // fp16 elems per k0 chunk
constexpr int NK0 = D / BK;            // 16 chunks
constexpr int NS = 4;                  // pipeline stages
constexpr int ROWB = 80;               // smem row stride bytes (64 data + 16 pad)
constexpr int ATILEB = 256 * ROWB;     // 20480
constexpr int BTILEB = 128 * ROWB;     // 10240
constexpr int STAGEB = ATILEB + BTILEB;          // 30720 (A, B)
constexpr int SMEM_DYN = NS * STAGEB;  // 122880

// attention smem layout (floats)
constexpr int QS_F = 64 * 50;          // 3200
constexpr int SP_F = 48 * 49;          // 2352 per group
constexpr int ATTN_SMEM = (2 * QS_F + 4 * SP_F) * 4;   // 63232 bytes
}

// ============================================================================
// Scratch (__device__ globals; no cudaMalloc allowed)
// ============================================================================
__device__ __half g_xq[(size_t)MTOT * D];   // inputs rounded to fp16
__device__ __half g_xk[(size_t)MTOT * D];
__device__ __half g_xv[(size_t)MTOT * D];
__device__ __half g_q[(size_t)MTOT * D];    // projections (fp16)
__device__ __half g_k[(size_t)MTOT * D];
__device__ __half g_v[(size_t)MTOT * D];
__device__ __half g_xo[(size_t)MTOT * D];   // attention out, fp16
__device__ __half g_wq[D * D];              // weights rounded to fp16
__device__ __half g_wk[D * D];
__device__ __half g_wo[D * D];

// ============================================================================
// PTX helpers (sm_90-compatible baseline PTX only — NO tcgen05; harness
// compiles PTX for compute_103 without the 'a' suffix)
// ============================================================================
__device__ __forceinline__ uint32_t smem_u32(const void* p) {
    uint32_t a;
    asm("{ .reg .u64 t; cvta.to.shared.u64 t, %1; cvt.u32.u64 %0, t; }"
        : "=r"(a) : "l"(p));
    return a;
}
__device__ __forceinline__ void cp_async16(uint32_t dst, const void* src) {
    asm volatile("cp.async.cg.shared.global [%0], [%1], 16;" :: "r"(dst), "l"(src));
}
__device__ __forceinline__ void cp_commit() {
    asm volatile("cp.async.commit_group;" ::: "memory");
}
template <int N>
__device__ __forceinline__ void cp_wait() {
    asm volatile("cp.async.wait_group %0;" :: "n"(N) : "memory");
}
__device__ __forceinline__ void ldsm4(uint32_t* r, uint32_t addr) {
    asm volatile("ldmatrix.sync.aligned.m8n8.x4.shared.b16 {%0,%1,%2,%3}, [%4];"
                 : "=r"(r[0]), "=r"(r[1]), "=r"(r[2]), "=r"(r[3]) : "r"(addr));
}
__device__ __forceinline__ void mma16816(float* c, const uint32_t* a,
                                         const uint32_t* b) {
    asm volatile(
        "mma.sync.aligned.m16n8k16.row.col.f32.f16.f16.f32 "
        "{%0,%1,%2,%3}, {%4,%5,%6,%7}, {%8,%9}, {%0,%1,%2,%3};"
        : "+f"(c[0]), "+f"(c[1]), "+f"(c[2]), "+f"(c[3])
        : "r"(a[0]), "r"(a[1]), "r"(a[2]), "r"(a[3]), "r"(b[0]), "r"(b[1]));
}

// ============================================================================
// conversions
// ============================================================================
__device__ __forceinline__ ushort4 to_h4(const float4 a) {
    ushort4 r;
    r.x = __half_as_ushort(__float2half(a.x));
    r.y = __half_as_ushort(__float2half(a.y));
    r.z = __half_as_ushort(__float2half(a.z));
    r.w = __half_as_ushort(__float2half(a.w));
    return r;
}
__device__ __forceinline__ float4 h4_to_f4(const ushort4 h) {
    float4 r;
    r.x = __half2float(__ushort_as_half(h.x));
    r.y = __half2float(__ushort_as_half(h.y));
    r.z = __half2float(__ushort_as_half(h.z));
    r.w = __half2float(__ushort_as_half(h.w));
    return r;
}

__global__ __launch_bounds__(256) void conv_inputs(
    const float* __restrict__ q, const float* __restrict__ k,
    const float* __restrict__ v)
{
    size_t i4 = (size_t)blockIdx.x * 256 + threadIdx.x;
    size_t idx = i4 * 4;
    *(ushort4*)(g_xq + idx) = to_h4(((const float4*)q)[i4]);
    *(ushort4*)(g_xk + idx) = to_h4(((const float4*)k)[i4]);
    *(ushort4*)(g_xv + idx) = to_h4(((const float4*)v)[i4]);
}

__global__ __launch_bounds__(256) void conv_weights(
    const float* __restrict__ wq, const float* __restrict__ wkv,
    const float* __restrict__ wo)
{
    size_t i4 = (size_t)blockIdx.x * 256 + threadIdx.x;
    size_t idx = i4 * 4;
    *(ushort4*)(g_wq + idx) = to_h4(((const float4*)wq)[i4]);
    *(ushort4*)(g_wk + idx) = to_h4(((const float4*)wkv)[i4]);
    *(ushort4*)(g_wo + idx) = to_h4(((const float4*)wo)[i4]);
}

// ============================================================================
// HMMA GEMM (fp16 1-term): C[m][n] = sum_d A[m][d]*W[n][d] + bias[n]
// BM=256 x BN=128, 512 threads (4x4 warp grid, 64x32 per warp), NS=4.
// Output: fp16 (WriteHalf) or fp32.
// ============================================================================
template <bool WriteHalf>
__device__ __forceinline__ void gemm_body(
    const __half* __restrict__ A, const __half* __restrict__ B,
    const float* __restrict__ bias, float* __restrict__ Cf,
    __half* __restrict__ Ch)
{
    extern __shared__ __align__(16) char dsm[];
    const uint32_t smem = smem_u32(dsm);
    __shared__ float bias_s[BN];

    const int tid = threadIdx.x;
    const int wid = tid >> 5, lane = tid & 31;
    const int wm = wid & 3, wn = wid >> 2;           // 4 x 4 warp grid
    const int n0 = blockIdx.x * BN;
    const int m0 = blockIdx.y * BM;

    if (tid < BN) bias_s[tid] = bias[n0 + tid];

    float acc[4][4][4];
#pragma unroll
    for (int i = 0; i < 4; i++)
#pragma unroll
        for (int j = 0; j < 4; j++)
#pragma unroll
            for (int e = 0; e < 4; e++) acc[i][j][e] = 0.0f;

    const int row = tid >> 2;        // 0..127
    const int c16 = tid & 3;

    auto load_chunk = [&](int c) {
        const int s = c % NS;
        const int k0 = c * BK;
        const uint32_t st = smem + (uint32_t)s * STAGEB;
        // A: 256 rows, 2 per thread
#pragma unroll
        for (int r = 0; r < 2; r++) {
            int rr = row + r * 128;
            cp_async16(st + rr * ROWB + c16 * 16,
                       A + (size_t)(m0 + rr) * D + k0 + c16 * 8);
        }
        // B: 128 rows, 1 per thread
        cp_async16(st + ATILEB + row * ROWB + c16 * 16,
                   B + (size_t)(n0 + row) * D + k0 + c16 * 8);
        cp_commit();
    };

    load_chunk(0);
    load_chunk(1);
    load_chunk(2);
    load_chunk(3);

    const uint32_t aLaneRow = (uint32_t)(wm * 64 + (lane & 15));
    const uint32_t aLaneOff = (uint32_t)(((lane >> 4) & 1) * 16);
    const uint32_t bLaneRow = (uint32_t)(wn * 32 + ((lane >> 4) & 1) * 8 + (lane & 7));
    const uint32_t bLaneOff = (uint32_t)(((lane >> 3) & 1) * 16);

    for (int c = 0; c < NK0; c++) {
        if (c <= NK0 - 4) cp_wait<3>();
        else if (c == NK0 - 3) cp_wait<2>();
        else if (c == NK0 - 2) cp_wait<1>();
        else cp_wait<0>();
        __syncthreads();

        const int s = c % NS;
        const uint32_t st = smem + (uint32_t)s * STAGEB;
        const uint32_t aAddr = st + aLaneRow * ROWB + aLaneOff;
        const uint32_t bAddr = st + ATILEB + bLaneRow * ROWB + bLaneOff;

#pragma unroll
        for (int ks = 0; ks < 2; ks++) {
            uint32_t a[4][4], b[2][4];
#pragma unroll
            for (int mf = 0; mf < 4; mf++)
                ldsm4(a[mf], aAddr + mf * 16 * ROWB + ks * 32);
#pragma unroll
            for (int bp = 0; bp < 2; bp++)
                ldsm4(b[bp], bAddr + bp * 16 * ROWB + ks * 32);
#pragma unroll
            for (int mf = 0; mf < 4; mf++)
#pragma unroll
                for (int nf = 0; nf < 4; nf++)
                    mma16816(acc[mf][nf], a[mf], &b[nf >> 1][(nf & 1) * 2]);
        }
        __syncthreads();
        if (c + 4 < NK0) load_chunk(c + 4);
    }

    // Epilogue
    const int gr = lane >> 2, tc = lane & 3;
#pragma unroll
    for (int mf = 0; mf < 4; mf++) {
#pragma unroll
        for (int nf = 0; nf < 4; nf++) {
            int rowo = m0 + wm * 64 + mf * 16 + gr;
            int coll = wn * 32 + nf * 8 + tc * 2;
            int col = n0 + coll;
            float b0 = bias_s[coll], b1 = bias_s[coll + 1];
            float v0 = acc[mf][nf][0] + b0, v1 = acc[mf][nf][1] + b1;
            float v2 = acc[mf][nf][2] + b0, v3 = acc[mf][nf][3] + b1;
            if (WriteHalf) {
                __half2 p0; p0.x = __float2half(v0); p0.y = __float2half(v1);
                __half2 p1; p1.x = __float2half(v2); p1.y = __float2half(v3);
                *(__half2*)(Ch + (size_t)rowo * D + col) = p0;
                *(__half2*)(Ch + (size_t)(rowo + 8) * D + col) = p1;
            } else {
                float2 p0; p0.x = v0; p0.y = v1;
                float2 p1; p1.x = v2; p1.y = v3;
                *(float2*)(Cf + (size_t)rowo * D + col) = p0;
                *(float2*)(Cf + (size_t)(rowo + 8) * D + col) = p1;
            }
        }
    }
}

__global__ __launch_bounds__(512) void gemm_qkv(const float* __restrict__ bq,
                                                const float* __restrict__ bkv)
{
    const int z = blockIdx.z;
    const __half* A = (z == 0) ? g_xq : (z == 1) ? g_xk : g_xv;
    const __half* B = (z == 0) ? g_wq : g_wk;
    const float* bias = (z == 0) ? bq : bkv;
    __half* C = (z == 0) ? g_q : (z == 1) ? g_k : g_v;
    gemm_body<true>(A, B, bias, nullptr, C);
}

__global__ __launch_bounds__(512) void gemm_out(const float* __restrict__ bo,
                                                float* __restrict__ out)
{
    gemm_body<false>(g_xo, g_wo, bo, out, nullptr);
}

// ============================================================================
// Fused per-patch attention (fp16 in, fp16 out; fp32 math).
// Stage 1: 4 k-groups x 64 threads (8x8), 6x6 register tiles.
// Stage 3: 16x16 grid, 3l x 4d register tiles.
// ============================================================================
__global__ __launch_bounds__(256) void attn_kernel()
{
    extern __shared__ __align__(16) float asm_f[];
    float* qs = asm_f;                 // [64][50]
    float* ks = asm_f + QS_F;          // [64][50]
    float* Sp = asm_f + 2 * QS_F;      // [4][48*49]

    const int patch = blockIdx.x;
    const size_t base = (size_t)patch * L * D;

    const int tid = threadIdx.x;
    const int g = tid >> 6;            // k-group 0..3
    const int t64 = tid & 63;
    const int px = t64 & 7;            // 8 col-groups of 6
    const int py = t64 >> 3;           // 8 row-groups of 6
    const int py6 = py * 6, px6 = px * 6;

    float s[6][6];
#pragma unroll
    for (int i = 0; i < 6; i++)
#pragma unroll
        for (int j = 0; j < 6; j++) s[i][j] = 0.0f;

    // ---- Stage 1: S = q k^T over D in chunks of 64 ----
    for (int d0 = 0; d0 < D; d0 += 64) {
#pragma unroll
        for (int r = 0; r < 3; r++) {
            int id = tid + r * 256;
            int rw = id >> 4;          // 0..47
            int c4 = id & 15;
            size_t gi = base + (size_t)rw * D + d0 + c4 * 4;
            float4 vq = h4_to_f4(*(const ushort4*)(g_q + gi));
            float4 vk = h4_to_f4(*(const ushort4*)(g_k + gi));
            qs[(c4 * 4 + 0) * 50 + rw] = vq.x;
            qs[(c4 * 4 + 1) * 50 + rw] = vq.y;
            qs[(c4 * 4 + 2) * 50 + rw] = vq.z;
            qs[(c4 * 4 + 3) * 50 + rw] = vq.w;
            ks[(c4 * 4 + 0) * 50 + rw] = vk.x;
            ks[(c4 * 4 + 1) * 50 + rw] = vk.y;
            ks[(c4 * 4 + 2) * 50 + rw] = vk.z;
            ks[(c4 * 4 + 3) * 50 + rw] = vk.w;
        }
        __syncthreads();

        const int kb0 = g * 16;
#pragma unroll
        for (int kk = 0; kk < 16; kk++) {
            const int kb = (kb0 + kk) * 50;
            float2 a01 = *(const float2*)&qs[kb + py6];
            float2 a23 = *(const float2*)&qs[kb + py6 + 2];
            float2 a45 = *(const float2*)&qs[kb + py6 + 4];
            float2 b01 = *(const float2*)&ks[kb + px6];
            float2 b23 = *(const float2*)&ks[kb + px6 + 2];
            float2 b45 = *(const float2*)&ks[kb + px6 + 4];
            float a6[6] = {a01.x, a01.y, a23.x, a23.y, a45.x, a45.y};
            float b6[6] = {b01.x, b01.y, b23.x, b23.y, b45.x, b45.y};
#pragma unroll
            for (int i = 0; i < 6; i++)
#pragma unroll
                for (int j = 0; j < 6; j++)
                    s[i][j] = fmaf(a6[i], b6[j], s[i][j]);
        }
        __syncthreads();
    }

    // write partials
#pragma unroll
    for (int i = 0; i < 6; i++)
#pragma unroll
        for (int j = 0; j < 6; j++)
            Sp[g * SP_F + (py6 + i) * 49 + px6 + j] = s[i][j];
    __syncthreads();

    // ---- Stage 2: reduce partials, mask + scale, softmax ----
    const float scale = 0.044194173824159216f;   // 512^-0.5
    for (int idx = tid; idx < 48 * 48; idx += 256) {
        int rw = idx / 48, cl = idx % 48;
        int o = rw * 49 + cl;
        float vv = Sp[o] + Sp[SP_F + o] + Sp[2 * SP_F + o] + Sp[3 * SP_F + o];
        Sp[o] = (rw == cl) ? -INFINITY : vv * scale;
    }
    __syncthreads();

    if (tid < 48) {
        float m = -INFINITY;
#pragma unroll
        for (int c = 0; c < 48; c++) m = fmaxf(m, Sp[tid * 49 + c]);
        float sum = 0.0f;
#pragma unroll
        for (int c = 0; c < 48; c++) {
            float e = __expf(Sp[tid * 49 + c] - m);
            Sp[tid * 49 + c] = e;
            sum += e;
        }
        float inv = 1.0f / sum;
#pragma unroll
        for (int c = 0; c < 48; c++) Sp[tid * 49 + c] *= inv;
    }
    __syncthreads();

    // ---- Stage 3: out = attn @ v, 3l x 4d register tiles ----
    float* vs = qs;   // 48*64 = 3072 <= QS_F
    const int dg = tid & 15;           // 16 dgroups x 4 cols
    const int lg = tid >> 4;           // 16 lgroups x 3 l
    for (int d0 = 0; d0 < D; d0 += 64) {
#pragma unroll
        for (int r = 0; r < 3; r++) {
            int id = tid + r * 256;
            int rw = id >> 4;
            int c4 = id & 15;
            size_t gi = base + (size_t)rw * D + d0 + c4 * 4;
            *(float4*)&vs[rw * 64 + c4 * 4] = h4_to_f4(*(const ushort4*)(g_v + gi));
        }
        __syncthreads();

        float acc3[3][4];
#pragma unroll
        for (int i = 0; i < 3; i++)
#pragma unroll
            for (int j = 0; j < 4; j++) acc3[i][j] = 0.0f;

#pragma unroll 8
        for (int m = 0; m < 48; m++) {
            float4 vv = *(const float4*)&vs[m * 64 + dg * 4];
#pragma unroll
            for (int i = 0; i < 3; i++) {
                float p = Sp[(lg * 3 + i) * 49 + m];
                acc3[i][0] = fmaf(p, vv.x, acc3[i][0]);
                acc3[i][1] = fmaf(p, vv.y, acc3[i][1]);
                acc3[i][2] = fmaf(p, vv.z, acc3[i][2]);
                acc3[i][3] = fmaf(p, vv.w, acc3[i][3]);
            }
        }

#pragma unroll
        for (int i = 0; i < 3; i++) {
            int l = lg * 3 + i;
            size_t oi = base + (size_t)l * D + d0 + dg * 4;
            ushort4 hv;
            hv.x = __half_as_ushort(__float2half(acc3[i][0]));
            hv.y = __half_as_ushort(__float2half(acc3[i][1]));
            hv.z = __half_as_ushort(__float2half(acc3[i][2]));
            hv.w = __half_as_ushort(__float2half(acc3[i][3]));
            *(ushort4*)(g_xo + oi) = hv;
        }
        __syncthreads();
    }
}

// ============================================================================
extern "C" void kernel_launch(void* const* d_in, const int* in_sizes, int n_in,
                              void* d_out, int out_size)
{
    const float* queries = (const float*)d_in[0];
    const float* keys    = (const float*)d_in[1];
    const float* values  = (const float*)d_in[2];
    const float* Wq      = (const float*)d_in[3];
    const float* bq      = (const float*)d_in[4];
    const float* Wkv     = (const float*)d_in[5];
    const float* bkv     = (const float*)d_in[6];
    const float* Wo      = (const float*)d_in[7];
    const float* bo      = (const float*)d_in[8];
    float* out = (float*)d_out;

    cudaFuncSetAttribute(gemm_qkv, cudaFuncAttributeMaxDynamicSharedMemorySize,
                         SMEM_DYN);
    cudaFuncSetAttribute(gemm_out, cudaFuncAttributeMaxDynamicSharedMemorySize,
                         SMEM_DYN);
    cudaFuncSetAttribute(attn_kernel, cudaFuncAttributeMaxDynamicSharedMemorySize,
                         ATTN_SMEM);

    conv_inputs<<<(int)(((size_t)MTOT * D / 4) / 256), 256>>>(queries, keys, values);
    conv_weights<<<(D * D / 4) / 256, 256>>>(Wq, Wkv, Wo);

    dim3 gqkv(D / BN, MTOT / BM, 3);
    gemm_qkv<<<gqkv, 512, SMEM_DYN>>>(bq, bkv);

    attn_kernel<<<NPATCH, 256, ATTN_SMEM>>>();

    dim3 gout(D / BN, MTOT / BM);
    gemm_out<<<gout, 512, SMEM_DYN>>>(bo, out);
}

// round 8
// speedup vs baseline: 5.4034x; 1.1928x over previous
#include <cuda_runtime.h>
#include <cuda_fp16.h>
#include <math.h>
#include <stdint.h>

// ============================================================================
// Problem constants
// ============================================================================
namespace {
constexpr int D = 512;
constexpr int L = 48;
constexpr int NPATCH = 8 * 7 * 24;     // 1344
constexpr int MTOT = NPATCH * L;       // 64512
constexpr int BM = 256, BN = 128;
constexpr int BK = 32;                 // fp16 elems per k0 chunk
constexpr int NK0 = D / BK;            // 16 chunks
constexpr int NS = 4;                  // pipeline stages
constexpr int ROWB = 80;               // smem row stride bytes (64 data + 16 pad)
constexpr int ATILEB = 256 * ROWB;     // 20480
constexpr int BTILEB = 128 * ROWB;     // 10240
constexpr int STAGEB = ATILEB + BTILEB;          // 30720 (A, B)
constexpr int SMEM_DYN = NS * STAGEB;  // 122880

// attention smem layout (bytes)
constexpr int QROWB = 272;             // 128 fp16 data + 16B pad (17 granules)
constexpr int QS_B = 64 * QROWB;       // 17408 (rows 48-63 garbage, discarded)
constexpr int KS_B = 48 * QROWB;       // 13056
constexpr int VS_B = 48 * QROWB;       // 13056
constexpr int SF_B = 48 * 49 * 4;      // 9408 (fp32 scores)
constexpr int P_ROWB = 112;            // 48 fp16 + 16B pad (7 granules)
constexpr int PH_B = 48 * P_ROWB;      // 5376
constexpr int QS_OFF = 0;
constexpr int KS_OFF = QS_OFF + QS_B;
constexpr int VS_OFF = KS_OFF + KS_B;
constexpr int SF_OFF = VS_OFF + VS_B;
constexpr int PH_OFF = SF_OFF + SF_B;
constexpr int PL_OFF = PH_OFF + PH_B;
constexpr int ATTN_SMEM = PL_OFF + PH_B;   // 63680
}

// ============================================================================
// Scratch (__device__ globals; no cudaMalloc allowed)
// ============================================================================
__device__ __half g_xq[(size_t)MTOT * D];   // inputs rounded to fp16
__device__ __half g_xk[(size_t)MTOT * D];
__device__ __half g_xv[(size_t)MTOT * D];
__device__ __half g_q[(size_t)MTOT * D];    // projections (fp16)
__device__ __half g_k[(size_t)MTOT * D];
__device__ __half g_v[(size_t)MTOT * D];
__device__ __half g_xo[(size_t)MTOT * D];   // attention out, fp16
__device__ __half g_wq[D * D];              // weights rounded to fp16
__device__ __half g_wk[D * D];
__device__ __half g_wo[D * D];

// ============================================================================
// PTX helpers (sm_90-compatible baseline PTX only — NO tcgen05; harness
// compiles PTX for compute_103 without the 'a' suffix)
// ============================================================================
__device__ __forceinline__ uint32_t smem_u32(const void* p) {
    uint32_t a;
    asm("{ .reg .u64 t; cvta.to.shared.u64 t, %1; cvt.u32.u64 %0, t; }"
        : "=r"(a) : "l"(p));
    return a;
}
__device__ __forceinline__ void cp_async16(uint32_t dst, const void* src) {
    asm volatile("cp.async.cg.shared.global [%0], [%1], 16;" :: "r"(dst), "l"(src));
}
__device__ __forceinline__ void cp_commit() {
    asm volatile("cp.async.commit_group;" ::: "memory");
}
template <int N>
__device__ __forceinline__ void cp_wait() {
    asm volatile("cp.async.wait_group %0;" :: "n"(N) : "memory");
}
__device__ __forceinline__ void ldsm4(uint32_t* r, uint32_t addr) {
    asm volatile("ldmatrix.sync.aligned.m8n8.x4.shared.b16 {%0,%1,%2,%3}, [%4];"
                 : "=r"(r[0]), "=r"(r[1]), "=r"(r[2]), "=r"(r[3]) : "r"(addr));
}
__device__ __forceinline__ void ldsm4t(uint32_t* r, uint32_t addr) {
    asm volatile("ldmatrix.sync.aligned.m8n8.x4.trans.shared.b16 {%0,%1,%2,%3}, [%4];"
                 : "=r"(r[0]), "=r"(r[1]), "=r"(r[2]), "=r"(r[3]) : "r"(addr));
}
__device__ __forceinline__ void mma16816(float* c, const uint32_t* a,
                                         const uint32_t* b) {
    asm volatile(
        "mma.sync.aligned.m16n8k16.row.col.f32.f16.f16.f32 "
        "{%0,%1,%2,%3}, {%4,%5,%6,%7}, {%8,%9}, {%0,%1,%2,%3};"
        : "+f"(c[0]), "+f"(c[1]), "+f"(c[2]), "+f"(c[3])
        : "r"(a[0]), "r"(a[1]), "r"(a[2]), "r"(a[3]), "r"(b[0]), "r"(b[1]));
}

// ============================================================================
// conversions
// ============================================================================
__device__ __forceinline__ ushort4 to_h4(const float4 a) {
    ushort4 r;
    r.x = __half_as_ushort(__float2half(a.x));
    r.y = __half_as_ushort(__float2half(a.y));
    r.z = __half_as_ushort(__float2half(a.z));
    r.w = __half_as_ushort(__float2half(a.w));
    return r;
}

__global__ __launch_bounds__(256) void conv_inputs(
    const float* __restrict__ q, const float* __restrict__ k,
    const float* __restrict__ v)
{
    size_t i4 = (size_t)blockIdx.x * 256 + threadIdx.x;
    size_t idx = i4 * 4;
    *(ushort4*)(g_xq + idx) = to_h4(((const float4*)q)[i4]);
    *(ushort4*)(g_xk + idx) = to_h4(((const float4*)k)[i4]);
    *(ushort4*)(g_xv + idx) = to_h4(((const float4*)v)[i4]);
}

__global__ __launch_bounds__(256) void conv_weights(
    const float* __restrict__ wq, const float* __restrict__ wkv,
    const float* __restrict__ wo)
{
    size_t i4 = (size_t)blockIdx.x * 256 + threadIdx.x;
    size_t idx = i4 * 4;
    *(ushort4*)(g_wq + idx) = to_h4(((const float4*)wq)[i4]);
    *(ushort4*)(g_wk + idx) = to_h4(((const float4*)wkv)[i4]);
    *(ushort4*)(g_wo + idx) = to_h4(((const float4*)wo)[i4]);
}

// ============================================================================
// HMMA GEMM (fp16 1-term): C[m][n] = sum_d A[m][d]*W[n][d] + bias[n]
// BM=256 x BN=128, 512 threads (4x4 warp grid, 64x32 per warp), NS=4.
// ============================================================================
template <bool WriteHalf>
__device__ __forceinline__ void gemm_body(
    const __half* __restrict__ A, const __half* __restrict__ B,
    const float* __restrict__ bias, float* __restrict__ Cf,
    __half* __restrict__ Ch)
{
    extern __shared__ __align__(16) char dsm[];
    const uint32_t smem = smem_u32(dsm);
    __shared__ float bias_s[BN];

    const int tid = threadIdx.x;
    const int wid = tid >> 5, lane = tid & 31;
    const int wm = wid & 3, wn = wid >> 2;           // 4 x 4 warp grid
    const int n0 = blockIdx.x * BN;
    const int m0 = blockIdx.y * BM;

    if (tid < BN) bias_s[tid] = bias[n0 + tid];

    float acc[4][4][4];
#pragma unroll
    for (int i = 0; i < 4; i++)
#pragma unroll
        for (int j = 0; j < 4; j++)
#pragma unroll
            for (int e = 0; e < 4; e++) acc[i][j][e] = 0.0f;

    const int row = tid >> 2;        // 0..127
    const int c16 = tid & 3;

    auto load_chunk = [&](int c) {
        const int s = c % NS;
        const int k0 = c * BK;
        const uint32_t st = smem + (uint32_t)s * STAGEB;
#pragma unroll
        for (int r = 0; r < 2; r++) {
            int rr = row + r * 128;
            cp_async16(st + rr * ROWB + c16 * 16,
                       A + (size_t)(m0 + rr) * D + k0 + c16 * 8);
        }
        cp_async16(st + ATILEB + row * ROWB + c16 * 16,
                   B + (size_t)(n0 + row) * D + k0 + c16 * 8);
        cp_commit();
    };

    load_chunk(0);
    load_chunk(1);
    load_chunk(2);
    load_chunk(3);

    const uint32_t aLaneRow = (uint32_t)(wm * 64 + (lane & 15));
    const uint32_t aLaneOff = (uint32_t)(((lane >> 4) & 1) * 16);
    const uint32_t bLaneRow = (uint32_t)(wn * 32 + ((lane >> 4) & 1) * 8 + (lane & 7));
    const uint32_t bLaneOff = (uint32_t)(((lane >> 3) & 1) * 16);

    for (int c = 0; c < NK0; c++) {
        if (c <= NK0 - 4) cp_wait<3>();
        else if (c == NK0 - 3) cp_wait<2>();
        else if (c == NK0 - 2) cp_wait<1>();
        else cp_wait<0>();
        __syncthreads();

        const int s = c % NS;
        const uint32_t st = smem + (uint32_t)s * STAGEB;
        const uint32_t aAddr = st + aLaneRow * ROWB + aLaneOff;
        const uint32_t bAddr = st + ATILEB + bLaneRow * ROWB + bLaneOff;

#pragma unroll
        for (int ks = 0; ks < 2; ks++) {
            uint32_t a[4][4], b[2][4];
#pragma unroll
            for (int mf = 0; mf < 4; mf++)
                ldsm4(a[mf], aAddr + mf * 16 * ROWB + ks * 32);
#pragma unroll
            for (int bp = 0; bp < 2; bp++)
                ldsm4(b[bp], bAddr + bp * 16 * ROWB + ks * 32);
#pragma unroll
            for (int mf = 0; mf < 4; mf++)
#pragma unroll
                for (int nf = 0; nf < 4; nf++)
                    mma16816(acc[mf][nf], a[mf], &b[nf >> 1][(nf & 1) * 2]);
        }
        __syncthreads();
        if (c + 4 < NK0) load_chunk(c + 4);
    }

    // Epilogue
    const int gr = lane >> 2, tc = lane & 3;
#pragma unroll
    for (int mf = 0; mf < 4; mf++) {
#pragma unroll
        for (int nf = 0; nf < 4; nf++) {
            int rowo = m0 + wm * 64 + mf * 16 + gr;
            int coll = wn * 32 + nf * 8 + tc * 2;
            int col = n0 + coll;
            float b0 = bias_s[coll], b1 = bias_s[coll + 1];
            float v0 = acc[mf][nf][0] + b0, v1 = acc[mf][nf][1] + b1;
            float v2 = acc[mf][nf][2] + b0, v3 = acc[mf][nf][3] + b1;
            if (WriteHalf) {
                __half2 p0; p0.x = __float2half(v0); p0.y = __float2half(v1);
                __half2 p1; p1.x = __float2half(v2); p1.y = __float2half(v3);
                *(__half2*)(Ch + (size_t)rowo * D + col) = p0;
                *(__half2*)(Ch + (size_t)(rowo + 8) * D + col) = p1;
            } else {
                float2 p0; p0.x = v0; p0.y = v1;
                float2 p1; p1.x = v2; p1.y = v3;
                *(float2*)(Cf + (size_t)rowo * D + col) = p0;
                *(float2*)(Cf + (size_t)(rowo + 8) * D + col) = p1;
            }
        }
    }
}

__global__ __launch_bounds__(512) void gemm_qkv(const float* __restrict__ bq,
                                                const float* __restrict__ bkv)
{
    const int z = blockIdx.z;
    const __half* A = (z == 0) ? g_xq : (z == 1) ? g_xk : g_xv;
    const __half* B = (z == 0) ? g_wq : g_wk;
    const float* bias = (z == 0) ? bq : bkv;
    __half* C = (z == 0) ? g_q : (z == 1) ? g_k : g_v;
    gemm_body<true>(A, B, bias, nullptr, C);
}

__global__ __launch_bounds__(512) void gemm_out(const float* __restrict__ bo,
                                                float* __restrict__ out)
{
    gemm_body<false>(g_xo, g_wo, bo, out, nullptr);
}

// ============================================================================
// HMMA fused per-patch attention.
//   S = q k^T via mma (fp16 in, fp32 acc) — exact given fp16 q,k.
//   softmax fp32 in smem (diag mask).
//   out = P @ v with P split hi/lo fp16 (2 MMA terms) — exact vs fp32.
// 8 warps: S: warp w -> m-band (w&3; band 3 discarded), n16 groups
// {0,2} for w<4 else {1}.  PV: warp w -> n16 d-group w, all 3 m-bands.
// ============================================================================
__global__ __launch_bounds__(256) void attn_kernel()
{
    extern __shared__ __align__(16) char smraw[];
    const uint32_t sm = smem_u32(smraw);
    const uint32_t qs = sm + QS_OFF, ks = sm + KS_OFF, vs = sm + VS_OFF;
    float* Sf = (float*)(smraw + SF_OFF);
    __half* Phc = (__half*)(smraw + PH_OFF);
    __half* Plc = (__half*)(smraw + PL_OFF);
    const uint32_t phA = sm + PH_OFF, plA = sm + PL_OFF;

    const int patch = blockIdx.x;
    const size_t base = (size_t)patch * L * D;
    const int tid = threadIdx.x;
    const int wid = tid >> 5, lane = tid & 31;
    const int mb = wid & 3;
    const int gr = lane >> 2, tc = lane & 3;

    const uint32_t aRowOff = (uint32_t)(mb * 16 + (lane & 15)) * QROWB;
    const uint32_t aOff = (uint32_t)(((lane >> 4) & 1) * 16);
    const uint32_t bRowBase = (uint32_t)(((lane >> 4) & 1) * 8 + (lane & 7));
    const uint32_t bOff = (uint32_t)(((lane >> 3) & 1) * 16);
    const int ng0 = (wid < 4) ? 0 : 1;
    const int ntiles = (wid < 4) ? 2 : 1;

    float accS[2][2][4];
#pragma unroll
    for (int t = 0; t < 2; t++)
#pragma unroll
        for (int j = 0; j < 2; j++)
#pragma unroll
            for (int e = 0; e < 4; e++) accS[t][j][e] = 0.0f;

    // ---- Stage 1: S = q k^T, 4 chunks of 128 ----
    for (int cc = 0; cc < 4; cc++) {
        const int d0 = cc * 128;
#pragma unroll
        for (int r = 0; r < 3; r++) {
            int id = tid + r * 256;
            int rw = id >> 4, g = id & 15;
            cp_async16(qs + rw * QROWB + g * 16, g_q + base + (size_t)rw * D + d0 + g * 8);
            cp_async16(ks + rw * QROWB + g * 16, g_k + base + (size_t)rw * D + d0 + g * 8);
        }
        cp_commit();
        cp_wait<0>();
        __syncthreads();

#pragma unroll
        for (int kk = 0; kk < 8; kk++) {
            uint32_t a[4];
            ldsm4(a, qs + aRowOff + kk * 32 + aOff);
#pragma unroll
            for (int t = 0; t < 2; t++) {
                if (t >= ntiles) break;
                int ng = ng0 + t * 2;
                uint32_t b[4];
                ldsm4(b, ks + (uint32_t)(ng * 16) * QROWB + bRowBase * QROWB + kk * 32 + bOff);
                mma16816(accS[t][0], a, &b[0]);
                mma16816(accS[t][1], a, &b[2]);
            }
        }
        __syncthreads();
    }

    // store S (band 3 discarded)
    if (mb < 3) {
#pragma unroll
        for (int t = 0; t < 2; t++) {
            if (t >= ntiles) break;
            int ng = ng0 + t * 2;
#pragma unroll
            for (int j = 0; j < 2; j++) {
                int col = ng * 16 + j * 8 + tc * 2;
                Sf[(mb * 16 + gr) * 49 + col]         = accS[t][j][0];
                Sf[(mb * 16 + gr) * 49 + col + 1]     = accS[t][j][1];
                Sf[(mb * 16 + gr + 8) * 49 + col]     = accS[t][j][2];
                Sf[(mb * 16 + gr + 8) * 49 + col + 1] = accS[t][j][3];
            }
        }
    }
    __syncthreads();

    // ---- Stage 2: softmax with diag mask ----
    if (tid < 48) {
        const float scale = 0.044194173824159216f;   // 512^-0.5
        float m = -INFINITY;
#pragma unroll
        for (int c = 0; c < 48; c++)
            if (c != tid) m = fmaxf(m, Sf[tid * 49 + c] * scale);
        float sum = 0.0f;
#pragma unroll
        for (int c = 0; c < 48; c++) {
            float e = (c == tid) ? 0.0f : __expf(Sf[tid * 49 + c] * scale - m);
            Sf[tid * 49 + c] = e;
            sum += e;
        }
        float inv = 1.0f / sum;
#pragma unroll
        for (int c = 0; c < 48; c++) Sf[tid * 49 + c] *= inv;
    }
    __syncthreads();

    // convert P to fp16 hi/lo (A-operand layout, 112B rows)
    for (int idx = tid; idx < 48 * 48; idx += 256) {
        int r = idx / 48, c = idx - r * 48;
        float p = Sf[r * 49 + c];
        __half hh = __float2half(p);
        Phc[r * (P_ROWB / 2) + c] = hh;
        Plc[r * (P_ROWB / 2) + c] = __float2half(p - __half2float(hh));
    }
    __syncthreads();

    // ---- Stage 3: out = P @ v, 4 chunks of 128 d-cols ----
    const int qd = lane >> 3;
    const uint32_t vRow = (uint32_t)((qd & 1) * 8 + (lane & 7));
    const uint32_t vCol = (uint32_t)(wid * 32 + (qd >> 1) * 16);
    const uint32_t pRow = (uint32_t)(lane & 15);

    for (int cc = 0; cc < 4; cc++) {
        const int d0 = cc * 128;
#pragma unroll
        for (int r = 0; r < 3; r++) {
            int id = tid + r * 256;
            int rw = id >> 4, g = id & 15;
            cp_async16(vs + rw * QROWB + g * 16, g_v + base + (size_t)rw * D + d0 + g * 8);
        }
        cp_commit();
        cp_wait<0>();
        __syncthreads();

        float acc[3][2][4];
#pragma unroll
        for (int i = 0; i < 3; i++)
#pragma unroll
            for (int j = 0; j < 2; j++)
#pragma unroll
                for (int e = 0; e < 4; e++) acc[i][j][e] = 0.0f;

#pragma unroll
        for (int kk = 0; kk < 3; kk++) {
            uint32_t b[4];
            ldsm4t(b, vs + (uint32_t)(kk * 16 + vRow) * QROWB + vCol);
#pragma unroll
            for (int mbb = 0; mbb < 3; mbb++) {
                uint32_t ah[4], al[4];
                ldsm4(ah, phA + (uint32_t)(mbb * 16 + pRow) * P_ROWB + kk * 32 + aOff);
                ldsm4(al, plA + (uint32_t)(mbb * 16 + pRow) * P_ROWB + kk * 32 + aOff);
                mma16816(acc[mbb][0], ah, &b[0]);
                mma16816(acc[mbb][1], ah, &b[2]);
                mma16816(acc[mbb][0], al, &b[0]);
                mma16816(acc[mbb][1], al, &b[2]);
            }
        }

#pragma unroll
        for (int mbb = 0; mbb < 3; mbb++)
#pragma unroll
            for (int j = 0; j < 2; j++) {
                int row = mbb * 16 + gr;
                int col = d0 + wid * 16 + j * 8 + tc * 2;
                __half2 p0, p1;
                p0.x = __float2half(acc[mbb][j][0]);
                p0.y = __float2half(acc[mbb][j][1]);
                p1.x = __float2half(acc[mbb][j][2]);
                p1.y = __float2half(acc[mbb][j][3]);
                *(__half2*)(g_xo + base + (size_t)row * D + col) = p0;
                *(__half2*)(g_xo + base + (size_t)(row + 8) * D + col) = p1;
            }
        __syncthreads();
    }
}

// ============================================================================
extern "C" void kernel_launch(void* const* d_in, const int* in_sizes, int n_in,
                              void* d_out, int out_size)
{
    const float* queries = (const float*)d_in[0];
    const float* keys    = (const float*)d_in[1];
    const float* values  = (const float*)d_in[2];
    const float* Wq      = (const float*)d_in[3];
    const float* bq      = (const float*)d_in[4];
    const float* Wkv     = (const float*)d_in[5];
    const float* bkv     = (const float*)d_in[6];
    const float* Wo      = (const float*)d_in[7];
    const float* bo      = (const float*)d_in[8];
    float* out = (float*)d_out;

    cudaFuncSetAttribute(gemm_qkv, cudaFuncAttributeMaxDynamicSharedMemorySize,
                         SMEM_DYN);
    cudaFuncSetAttribute(gemm_out, cudaFuncAttributeMaxDynamicSharedMemorySize,
                         SMEM_DYN);
    cudaFuncSetAttribute(attn_kernel, cudaFuncAttributeMaxDynamicSharedMemorySize,
                         ATTN_SMEM);

    conv_inputs<<<(int)(((size_t)MTOT * D / 4) / 256), 256>>>(queries, keys, values);
    conv_weights<<<(D * D / 4) / 256, 256>>>(Wq, Wkv, Wo);

    dim3 gqkv(D / BN, MTOT / BM, 3);
    gemm_qkv<<<gqkv, 512, SMEM_DYN>>>(bq, bkv);

    attn_kernel<<<NPATCH, 256, ATTN_SMEM>>>();

    dim3 gout(D / BN, MTOT / BM);
    gemm_out<<<gout, 512, SMEM_DYN>>>(bo, out);
}

// round 9
// speedup vs baseline: 6.4144x; 1.1871x over previous
#include <cuda_runtime.h>
#include <cuda_fp16.h>
#include <math.h>
#include <stdint.h>

// ============================================================================
// Problem constants
// ============================================================================
namespace {
constexpr int D = 512;
constexpr int L = 48;
constexpr int NPATCH = 8 * 7 * 24;     // 1344
constexpr int MTOT = NPATCH * L;       // 64512
constexpr int BM = 128, BN = 128;
constexpr int BK = 64;                 // fp16 elems per chunk
constexpr int NK0 = D / BK;            // 8 chunks
constexpr int NS = 3;                  // pipeline stages
constexpr int ROWB = 144;              // 128 data bytes + 16 pad (9 granules)
constexpr int ATILEB = 128 * ROWB;     // 18432
constexpr int STAGEB = 2 * ATILEB;     // 36864 (A + B)
constexpr int SMEM_DYN = NS * STAGEB;  // 110592  -> 2 CTAs/SM

// attention smem layout (bytes)
constexpr int QROWB = 272;             // 128 fp16 data + 16B pad (17 granules)
constexpr int QS_B = 64 * QROWB;       // (rows 48-63 garbage, discarded)
constexpr int KS_B = 48 * QROWB;
constexpr int VS_B = 48 * QROWB;
constexpr int SF_B = 48 * 49 * 4;
constexpr int P_ROWB = 112;            // 48 fp16 + 16B pad (7 granules)
constexpr int PH_B = 48 * P_ROWB;
constexpr int QS_OFF = 0;
constexpr int KS_OFF = QS_OFF + QS_B;
constexpr int VS_OFF = KS_OFF + KS_B;
constexpr int SF_OFF = VS_OFF + VS_B;
constexpr int PH_OFF = SF_OFF + SF_B;
constexpr int PL_OFF = PH_OFF + PH_B;
constexpr int ATTN_SMEM = PL_OFF + PH_B;   // 63680
}

// ============================================================================
// Scratch (__device__ globals; no cudaMalloc allowed)
// ============================================================================
__device__ __half g_xq[(size_t)MTOT * D];   // inputs rounded to fp16
__device__ __half g_xk[(size_t)MTOT * D];
__device__ __half g_xv[(size_t)MTOT * D];
__device__ __half g_q[(size_t)MTOT * D];    // projections (fp16)
__device__ __half g_k[(size_t)MTOT * D];
__device__ __half g_v[(size_t)MTOT * D];
__device__ __half g_xo[(size_t)MTOT * D];   // attention out, fp16
__device__ __half g_wq[D * D];              // weights rounded to fp16
__device__ __half g_wk[D * D];
__device__ __half g_wo[D * D];

// ============================================================================
// PTX helpers (sm_90-compatible baseline PTX only — NO tcgen05; harness
// compiles PTX for compute_103 without the 'a' suffix)
// ============================================================================
__device__ __forceinline__ uint32_t smem_u32(const void* p) {
    uint32_t a;
    asm("{ .reg .u64 t; cvta.to.shared.u64 t, %1; cvt.u32.u64 %0, t; }"
        : "=r"(a) : "l"(p));
    return a;
}
__device__ __forceinline__ void cp_async16(uint32_t dst, const void* src) {
    asm volatile("cp.async.cg.shared.global [%0], [%1], 16;" :: "r"(dst), "l"(src));
}
__device__ __forceinline__ void cp_commit() {
    asm volatile("cp.async.commit_group;" ::: "memory");
}
template <int N>
__device__ __forceinline__ void cp_wait() {
    asm volatile("cp.async.wait_group %0;" :: "n"(N) : "memory");
}
__device__ __forceinline__ void ldsm4(uint32_t* r, uint32_t addr) {
    asm volatile("ldmatrix.sync.aligned.m8n8.x4.shared.b16 {%0,%1,%2,%3}, [%4];"
                 : "=r"(r[0]), "=r"(r[1]), "=r"(r[2]), "=r"(r[3]) : "r"(addr));
}
__device__ __forceinline__ void ldsm4t(uint32_t* r, uint32_t addr) {
    asm volatile("ldmatrix.sync.aligned.m8n8.x4.trans.shared.b16 {%0,%1,%2,%3}, [%4];"
                 : "=r"(r[0]), "=r"(r[1]), "=r"(r[2]), "=r"(r[3]) : "r"(addr));
}
__device__ __forceinline__ void mma16816(float* c, const uint32_t* a,
                                         const uint32_t* b) {
    asm volatile(
        "mma.sync.aligned.m16n8k16.row.col.f32.f16.f16.f32 "
        "{%0,%1,%2,%3}, {%4,%5,%6,%7}, {%8,%9}, {%0,%1,%2,%3};"
        : "+f"(c[0]), "+f"(c[1]), "+f"(c[2]), "+f"(c[3])
        : "r"(a[0]), "r"(a[1]), "r"(a[2]), "r"(a[3]), "r"(b[0]), "r"(b[1]));
}

// ============================================================================
// conversions
// ============================================================================
__device__ __forceinline__ ushort4 to_h4(const float4 a) {
    ushort4 r;
    r.x = __half_as_ushort(__float2half(a.x));
    r.y = __half_as_ushort(__float2half(a.y));
    r.z = __half_as_ushort(__float2half(a.z));
    r.w = __half_as_ushort(__float2half(a.w));
    return r;
}

__global__ __launch_bounds__(256) void conv_inputs(
    const float* __restrict__ q, const float* __restrict__ k,
    const float* __restrict__ v)
{
    size_t i4 = (size_t)blockIdx.x * 256 + threadIdx.x;
    size_t idx = i4 * 4;
    *(ushort4*)(g_xq + idx) = to_h4(((const float4*)q)[i4]);
    *(ushort4*)(g_xk + idx) = to_h4(((const float4*)k)[i4]);
    *(ushort4*)(g_xv + idx) = to_h4(((const float4*)v)[i4]);
}

__global__ __launch_bounds__(256) void conv_weights(
    const float* __restrict__ wq, const float* __restrict__ wkv,
    const float* __restrict__ wo)
{
    size_t i4 = (size_t)blockIdx.x * 256 + threadIdx.x;
    size_t idx = i4 * 4;
    *(ushort4*)(g_wq + idx) = to_h4(((const float4*)wq)[i4]);
    *(ushort4*)(g_wk + idx) = to_h4(((const float4*)wkv)[i4]);
    *(ushort4*)(g_wo + idx) = to_h4(((const float4*)wo)[i4]);
}

// ============================================================================
// HMMA GEMM (fp16 1-term): C[m][n] = sum_d A[m][d]*W[n][d] + bias[n]
// BM=128 x BN=128 x BK=64, 256 threads (2x4 warp grid, 64x32 per warp),
// NS=3 pipeline, ONE __syncthreads per chunk, 2 CTAs/SM.
// ============================================================================
template <bool WriteHalf>
__device__ __forceinline__ void gemm_body(
    const __half* __restrict__ A, const __half* __restrict__ B,
    const float* __restrict__ bias, float* __restrict__ Cf,
    __half* __restrict__ Ch)
{
    extern __shared__ __align__(16) char dsm[];
    const uint32_t smem = smem_u32(dsm);
    __shared__ float bias_s[BN];

    const int tid = threadIdx.x;
    const int wid = tid >> 5, lane = tid & 31;
    const int wm = wid & 1, wn = wid >> 1;           // 2 x 4 warp grid
    const int n0 = blockIdx.x * BN;
    const int m0 = blockIdx.y * BM;

    if (tid < BN) bias_s[tid] = bias[n0 + tid];

    float acc[4][4][4];
#pragma unroll
    for (int i = 0; i < 4; i++)
#pragma unroll
        for (int j = 0; j < 4; j++)
#pragma unroll
            for (int e = 0; e < 4; e++) acc[i][j][e] = 0.0f;

    auto load_chunk = [&](int c) {
        const int s = c % NS;
        const int k0 = c * BK;
        const uint32_t st = smem + (uint32_t)s * STAGEB;
#pragma unroll
        for (int r = 0; r < 4; r++) {
            int id = tid + r * 256;          // 0..1023
            int row = id >> 3, g = id & 7;
            cp_async16(st + row * ROWB + g * 16,
                       A + (size_t)(m0 + row) * D + k0 + g * 8);
            cp_async16(st + ATILEB + row * ROWB + g * 16,
                       B + (size_t)(n0 + row) * D + k0 + g * 8);
        }
        cp_commit();
    };

    load_chunk(0);
    load_chunk(1);

    const uint32_t aLaneRow = (uint32_t)(wm * 64 + (lane & 15));
    const uint32_t aLaneOff = (uint32_t)(((lane >> 4) & 1) * 16);
    const uint32_t bLaneRow = (uint32_t)(wn * 32 + ((lane >> 4) & 1) * 8 + (lane & 7));
    const uint32_t bLaneOff = (uint32_t)(((lane >> 3) & 1) * 16);

    for (int c = 0; c < NK0; c++) {
        if (c == NK0 - 1) cp_wait<0>();
        else cp_wait<1>();
        __syncthreads();                     // all warps done reading buf (c-1)%NS
        if (c + NS - 1 < NK0) load_chunk(c + NS - 1);   // writes buf (c-1)%NS

        const int s = c % NS;
        const uint32_t st = smem + (uint32_t)s * STAGEB;
        const uint32_t aAddr = st + aLaneRow * ROWB + aLaneOff;
        const uint32_t bAddr = st + ATILEB + bLaneRow * ROWB + bLaneOff;

#pragma unroll
        for (int ks = 0; ks < 4; ks++) {
            uint32_t a[4][4], b[2][4];
#pragma unroll
            for (int mf = 0; mf < 4; mf++)
                ldsm4(a[mf], aAddr + mf * 16 * ROWB + ks * 32);
#pragma unroll
            for (int bp = 0; bp < 2; bp++)
                ldsm4(b[bp], bAddr + bp * 16 * ROWB + ks * 32);
#pragma unroll
            for (int mf = 0; mf < 4; mf++)
#pragma unroll
                for (int nf = 0; nf < 4; nf++)
                    mma16816(acc[mf][nf], a[mf], &b[nf >> 1][(nf & 1) * 2]);
        }
    }

    // Epilogue
    const int gr = lane >> 2, tc = lane & 3;
#pragma unroll
    for (int mf = 0; mf < 4; mf++) {
#pragma unroll
        for (int nf = 0; nf < 4; nf++) {
            int rowo = m0 + wm * 64 + mf * 16 + gr;
            int coll = wn * 32 + nf * 8 + tc * 2;
            int col = n0 + coll;
            float b0 = bias_s[coll], b1 = bias_s[coll + 1];
            float v0 = acc[mf][nf][0] + b0, v1 = acc[mf][nf][1] + b1;
            float v2 = acc[mf][nf][2] + b0, v3 = acc[mf][nf][3] + b1;
            if (WriteHalf) {
                __half2 p0; p0.x = __float2half(v0); p0.y = __float2half(v1);
                __half2 p1; p1.x = __float2half(v2); p1.y = __float2half(v3);
                *(__half2*)(Ch + (size_t)rowo * D + col) = p0;
                *(__half2*)(Ch + (size_t)(rowo + 8) * D + col) = p1;
            } else {
                float2 p0; p0.x = v0; p0.y = v1;
                float2 p1; p1.x = v2; p1.y = v3;
                *(float2*)(Cf + (size_t)rowo * D + col) = p0;
                *(float2*)(Cf + (size_t)(rowo + 8) * D + col) = p1;
            }
        }
    }
}

__global__ __launch_bounds__(256, 2) void gemm_qkv(const float* __restrict__ bq,
                                                   const float* __restrict__ bkv)
{
    const int z = blockIdx.z;
    const __half* A = (z == 0) ? g_xq : (z == 1) ? g_xk : g_xv;
    const __half* B = (z == 0) ? g_wq : g_wk;
    const float* bias = (z == 0) ? bq : bkv;
    __half* C = (z == 0) ? g_q : (z == 1) ? g_k : g_v;
    gemm_body<true>(A, B, bias, nullptr, C);
}

__global__ __launch_bounds__(256, 2) void gemm_out(const float* __restrict__ bo,
                                                   float* __restrict__ out)
{
    gemm_body<false>(g_xo, g_wo, bo, out, nullptr);
}

// ============================================================================
// HMMA fused per-patch attention (unchanged from round 8).
// ============================================================================
__global__ __launch_bounds__(256) void attn_kernel()
{
    extern __shared__ __align__(16) char smraw[];
    const uint32_t sm = smem_u32(smraw);
    const uint32_t qs = sm + QS_OFF, ks = sm + KS_OFF, vs = sm + VS_OFF;
    float* Sf = (float*)(smraw + SF_OFF);
    __half* Phc = (__half*)(smraw + PH_OFF);
    __half* Plc = (__half*)(smraw + PL_OFF);
    const uint32_t phA = sm + PH_OFF, plA = sm + PL_OFF;

    const int patch = blockIdx.x;
    const size_t base = (size_t)patch * L * D;
    const int tid = threadIdx.x;
    const int wid = tid >> 5, lane = tid & 31;
    const int mb = wid & 3;
    const int gr = lane >> 2, tc = lane & 3;

    const uint32_t aRowOff = (uint32_t)(mb * 16 + (lane & 15)) * QROWB;
    const uint32_t aOff = (uint32_t)(((lane >> 4) & 1) * 16);
    const uint32_t bRowBase = (uint32_t)(((lane >> 4) & 1) * 8 + (lane & 7));
    const uint32_t bOff = (uint32_t)(((lane >> 3) & 1) * 16);
    const int ng0 = (wid < 4) ? 0 : 1;
    const int ntiles = (wid < 4) ? 2 : 1;

    float accS[2][2][4];
#pragma unroll
    for (int t = 0; t < 2; t++)
#pragma unroll
        for (int j = 0; j < 2; j++)
#pragma unroll
            for (int e = 0; e < 4; e++) accS[t][j][e] = 0.0f;

    // ---- Stage 1: S = q k^T, 4 chunks of 128 ----
    for (int cc = 0; cc < 4; cc++) {
        const int d0 = cc * 128;
#pragma unroll
        for (int r = 0; r < 3; r++) {
            int id = tid + r * 256;
            int rw = id >> 4, g = id & 15;
            cp_async16(qs + rw * QROWB + g * 16, g_q + base + (size_t)rw * D + d0 + g * 8);
            cp_async16(ks + rw * QROWB + g * 16, g_k + base + (size_t)rw * D + d0 + g * 8);
        }
        cp_commit();
        cp_wait<0>();
        __syncthreads();

#pragma unroll
        for (int kk = 0; kk < 8; kk++) {
            uint32_t a[4];
            ldsm4(a, qs + aRowOff + kk * 32 + aOff);
#pragma unroll
            for (int t = 0; t < 2; t++) {
                if (t >= ntiles) break;
                int ng = ng0 + t * 2;
                uint32_t b[4];
                ldsm4(b, ks + (uint32_t)(ng * 16) * QROWB + bRowBase * QROWB + kk * 32 + bOff);
                mma16816(accS[t][0], a, &b[0]);
                mma16816(accS[t][1], a, &b[2]);
            }
        }
        __syncthreads();
    }

    // store S (band 3 discarded)
    if (mb < 3) {
#pragma unroll
        for (int t = 0; t < 2; t++) {
            if (t >= ntiles) break;
            int ng = ng0 + t * 2;
#pragma unroll
            for (int j = 0; j < 2; j++) {
                int col = ng * 16 + j * 8 + tc * 2;
                Sf[(mb * 16 + gr) * 49 + col]         = accS[t][j][0];
                Sf[(mb * 16 + gr) * 49 + col + 1]     = accS[t][j][1];
                Sf[(mb * 16 + gr + 8) * 49 + col]     = accS[t][j][2];
                Sf[(mb * 16 + gr + 8) * 49 + col + 1] = accS[t][j][3];
            }
        }
    }
    __syncthreads();

    // ---- Stage 2: softmax with diag mask ----
    if (tid < 48) {
        const float scale = 0.044194173824159216f;   // 512^-0.5
        float m = -INFINITY;
#pragma unroll
        for (int c = 0; c < 48; c++)
            if (c != tid) m = fmaxf(m, Sf[tid * 49 + c] * scale);
        float sum = 0.0f;
#pragma unroll
        for (int c = 0; c < 48; c++) {
            float e = (c == tid) ? 0.0f : __expf(Sf[tid * 49 + c] * scale - m);
            Sf[tid * 49 + c] = e;
            sum += e;
        }
        float inv = 1.0f / sum;
#pragma unroll
        for (int c = 0; c < 48; c++) Sf[tid * 49 + c] *= inv;
    }
    __syncthreads();

    // convert P to fp16 hi/lo (A-operand layout, 112B rows)
    for (int idx = tid; idx < 48 * 48; idx += 256) {
        int r = idx / 48, c = idx - r * 48;
        float p = Sf[r * 49 + c];
        __half hh = __float2half(p);
        Phc[r * (P_ROWB / 2) + c] = hh;
        Plc[r * (P_ROWB / 2) + c] = __float2half(p - __half2float(hh));
    }
    __syncthreads();

    // ---- Stage 3: out = P @ v, 4 chunks of 128 d-cols ----
    const int qd = lane >> 3;
    const uint32_t vRow = (uint32_t)((qd & 1) * 8 + (lane & 7));
    const uint32_t vCol = (uint32_t)(wid * 32 + (qd >> 1) * 16);
    const uint32_t pRow = (uint32_t)(lane & 15);

    for (int cc = 0; cc < 4; cc++) {
        const int d0 = cc * 128;
#pragma unroll
        for (int r = 0; r < 3; r++) {
            int id = tid + r * 256;
            int rw = id >> 4, g = id & 15;
            cp_async16(vs + rw * QROWB + g * 16, g_v + base + (size_t)rw * D + d0 + g * 8);
        }
        cp_commit();
        cp_wait<0>();
        __syncthreads();

        float acc[3][2][4];
#pragma unroll
        for (int i = 0; i < 3; i++)
#pragma unroll
            for (int j = 0; j < 2; j++)
#pragma unroll
                for (int e = 0; e < 4; e++) acc[i][j][e] = 0.0f;

#pragma unroll
        for (int kk = 0; kk < 3; kk++) {
            uint32_t b[4];
            ldsm4t(b, vs + (uint32_t)(kk * 16 + vRow) * QROWB + vCol);
#pragma unroll
            for (int mbb = 0; mbb < 3; mbb++) {
                uint32_t ah[4], al[4];
                ldsm4(ah, phA + (uint32_t)(mbb * 16 + pRow) * P_ROWB + kk * 32 + aOff);
                ldsm4(al, plA + (uint32_t)(mbb * 16 + pRow) * P_ROWB + kk * 32 + aOff);
                mma16816(acc[mbb][0], ah, &b[0]);
                mma16816(acc[mbb][1], ah, &b[2]);
                mma16816(acc[mbb][0], al, &b[0]);
                mma16816(acc[mbb][1], al, &b[2]);
            }
        }

#pragma unroll
        for (int mbb = 0; mbb < 3; mbb++)
#pragma unroll
            for (int j = 0; j < 2; j++) {
                int row = mbb * 16 + gr;
                int col = d0 + wid * 16 + j * 8 + tc * 2;
                __half2 p0, p1;
                p0.x = __float2half(acc[mbb][j][0]);
                p0.y = __float2half(acc[mbb][j][1]);
                p1.x = __float2half(acc[mbb][j][2]);
                p1.y = __float2half(acc[mbb][j][3]);
                *(__half2*)(g_xo + base + (size_t)row * D + col) = p0;
                *(__half2*)(g_xo + base + (size_t)(row + 8) * D + col) = p1;
            }
        __syncthreads();
    }
}

// ============================================================================
extern "C" void kernel_launch(void* const* d_in, const int* in_sizes, int n_in,
                              void* d_out, int out_size)
{
    const float* queries = (const float*)d_in[0];
    const float* keys    = (const float*)d_in[1];
    const float* values  = (const float*)d_in[2];
    const float* Wq      = (const float*)d_in[3];
    const float* bq      = (const float*)d_in[4];
    const float* Wkv     = (const float*)d_in[5];
    const float* bkv     = (const float*)d_in[6];
    const float* Wo      = (const float*)d_in[7];
    const float* bo      = (const float*)d_in[8];
    float* out = (float*)d_out;

    cudaFuncSetAttribute(gemm_qkv, cudaFuncAttributeMaxDynamicSharedMemorySize,
                         SMEM_DYN);
    cudaFuncSetAttribute(gemm_out, cudaFuncAttributeMaxDynamicSharedMemorySize,
                         SMEM_DYN);
    cudaFuncSetAttribute(attn_kernel, cudaFuncAttributeMaxDynamicSharedMemorySize,
                         ATTN_SMEM);

    conv_inputs<<<(int)(((size_t)MTOT * D / 4) / 256), 256>>>(queries, keys, values);
    conv_weights<<<(D * D / 4) / 256, 256>>>(Wq, Wkv, Wo);

    dim3 gqkv(D / BN, MTOT / BM, 3);
    gemm_qkv<<<gqkv, 256, SMEM_DYN>>>(bq, bkv);

    attn_kernel<<<NPATCH, 256, ATTN_SMEM>>>();

    dim3 gout(D / BN, MTOT / BM);
    gemm_out<<<gout, 256, SMEM_DYN>>>(bo, out);
}